// round 11
// baseline (speedup 1.0000x reference)
#include <cuda.h>
#include <cuda_runtime.h>
#include <cstdint>

typedef unsigned long long u64;

__device__ __align__(256) float g_bufA[8388608];
__device__ __align__(256) float g_bufB[4194304];
__device__ __align__(256) float g_wT [21971520];   // transposed weights [c][ij][o]

__device__ __forceinline__ void cp_async16(uint32_t saddr, const float* gptr) {
    asm volatile("cp.async.cg.shared.global [%0], [%1], 16;" :: "r"(saddr), "l"(gptr));
}
#define CP_COMMIT() asm volatile("cp.async.commit_group;" ::: "memory")
#define CP_WAIT0()  asm volatile("cp.async.wait_group 0;" ::: "memory")
#define FFMA2(acc, w, v) asm("fma.rn.f32x2 %0, %1, %2, %0;" : "+l"(acc) : "l"(w), "l"(v))
#define PACK2(d, a, b)   asm("mov.b64 %0, {%1, %2};" : "=l"(d) : "f"(a), "f"(b))
#define UNPACK2(lo, hi, p) asm("mov.b64 {%0, %1}, %2;" : "=f"(lo), "=f"(hi) : "l"(p))

#define MBAR_INIT(mbar, cnt) \
    asm volatile("mbarrier.init.shared.b64 [%0], %1;" :: "r"(mbar), "r"(cnt) : "memory")
#define MBAR_EXPECT(mbar, bytes) \
    asm volatile("mbarrier.arrive.expect_tx.shared.b64 _, [%0], %1;" :: "r"(mbar), "r"(bytes) : "memory")
#define MBAR_WAIT(mbar, par) do { \
    asm volatile( \
        "{\n\t.reg .pred P1;\n\t" \
        "WAIT_LOOP_%=:\n\t" \
        "mbarrier.try_wait.parity.acquire.cta.shared::cta.b64 P1, [%0], %1, 0x989680;\n\t" \
        "@P1 bra.uni WAIT_DONE_%=;\n\t" \
        "bra.uni WAIT_LOOP_%=;\n\t" \
        "WAIT_DONE_%=:\n\t}" \
        :: "r"(mbar), "r"(par) : "memory"); \
} while(0)
#define TMA3D(dst, tmapp, cx, cy, cz, mbar) \
    asm volatile("cp.async.bulk.tensor.3d.shared::cta.global.tile.mbarrier::complete_tx::bytes " \
        "[%0], [%1, {%2, %3, %4}], [%5];" \
        :: "r"(dst), "l"(tmapp), "r"(cx), "r"(cy), "r"(cz), "r"(mbar) : "memory")

// ─── fused weight transpose: one launch for all 14 layers ───
struct WPtrs { const float* p[14]; };

__global__ void transpose_all_kernel(WPtrs wp, float* __restrict__ wt)
{
    const int i = blockIdx.x * 256 + threadIdx.x;
    if (i >= 21971520) return;
    const int CiA[14] = {1,64,64, 64,128,128, 128,256,256, 256,512,512, 512,1024};
    const int CoA[14] = {64,64,64, 128,128,128, 256,256,256, 512,512,512, 1024,1024};
    const int OFF[15] = {0,576,37440,74304,148032,295488,442944,737856,1327680,
                         1917504,3097152,5456448,7815744,12534336,21971520};
    int l = 0;
    #pragma unroll
    for (int k = 1; k < 14; k++) if (i >= OFF[k]) l = k;
    int j = i - OFF[l];
    int Co = CoA[l], Ci = CiA[l];
    int o = j % Co;
    int cij = j / Co;
    int c = cij / 9, ij = cij % 9;
    wt[i] = wp.p[l][((size_t)o * Ci + c) * 9 + ij];
}

#define TAP16R(w0, w1, w2, w3, vv, A)                                  \
    {                                                                  \
        FFMA2((A)[0], (w0).x, vv); FFMA2((A)[1], (w0).y, vv);          \
        FFMA2((A)[2], (w1).x, vv); FFMA2((A)[3], (w1).y, vv);          \
        FFMA2((A)[4], (w2).x, vv); FFMA2((A)[5], (w2).y, vv);          \
        FFMA2((A)[6], (w3).x, vv); FFMA2((A)[7], (w3).y, vv);          \
    }

// ─── stride-1, wide images (W>=32): 32x16 tile, 2 px/thread, 16 outs ───
// TMA tile 40x18 = 720 floats (2880 B); SMEM channel stride padded to 736 floats (128B mult).
template<int CB>
__global__ void __launch_bounds__(256) conv_s1(
    const __grid_constant__ CUtensorMap tmap, const float* __restrict__ wt,
    const float* __restrict__ bias, const float* __restrict__ kern,
    float* __restrict__ out, int Ci, int Co, int H, int W, int tilesX)
{
    constexpr int PITCH = 40, TSZ = 18 * 40 /*720*/, CSZ = 736;
    __shared__ __align__(128) float s_in[2][CB * CSZ];
    __shared__ __align__(16) float s_w[2][CB * 144];
    __shared__ __align__(8) unsigned long long s_mbar[2];

    const int tid = threadIdx.x;
    const int lx = tid % 16, ty = tid / 16;
    const int tX = blockIdx.x % tilesX, tY = blockIdx.x / tilesX;
    const int ocg = blockIdx.y, b = blockIdx.z;
    const int oh = tY * 16 + ty, ow0 = tX * 32 + 2 * lx;
    const size_t HW = (size_t)H * W;
    const int gr0 = tY * 16 - 1, gc0 = tX * 32 - 4;

    const uint32_t mb0 = (uint32_t)__cvta_generic_to_shared(&s_mbar[0]);
    if (tid == 0) { MBAR_INIT(mb0, 1); MBAR_INIT(mb0 + 8, 1); }

    float k0[9], k1[9];
    if (kern) {
        const float* kp = kern + (size_t)b * 9 * HW + (size_t)oh * W + ow0;
        #pragma unroll
        for (int t = 0; t < 9; t++) {
            float2 kk = *(const float2*)(kp + (size_t)t * HW);
            k0[t] = kk.x; k1[t] = kk.y;
        }
    } else {
        #pragma unroll
        for (int t = 0; t < 9; t++) { k0[t] = 1.0f; k1[t] = 1.0f; }
    }

    u64 accA[8], accB[8];
    #pragma unroll
    for (int p = 0; p < 8; p++) { accA[p] = 0ull; accB[p] = 0ull; }

    const uint32_t sinA[2] = {(uint32_t)__cvta_generic_to_shared(&s_in[0][0]),
                              (uint32_t)__cvta_generic_to_shared(&s_in[1][0])};
    const uint32_t swA[2]  = {(uint32_t)__cvta_generic_to_shared(&s_w[0][0]),
                              (uint32_t)__cvta_generic_to_shared(&s_w[1][0])};
    const int NG = Ci / CB;

    const bool wval = tid < CB * 36;
    uint32_t woff = 0;
    const float* wsrc = wt;
    {
        int c = tid / 36, rem = tid % 36, ij = rem / 4, q = rem % 4;
        woff = (uint32_t)(c * 144 + ij * 16 + 4 * q) * 4u;
        wsrc = wt + ((size_t)c * 9 + ij) * Co + (size_t)ocg * 16 + 4 * q;
    }
    const size_t wstep = (size_t)CB * 9 * Co;

    __syncthreads();   // mbarrier init visible

    auto stage_in = [&](int g, int buf) {
        uint32_t mb = mb0 + buf * 8;
        MBAR_EXPECT(mb, (uint32_t)(CB * TSZ * 4));
        int plane = b * Ci + g * CB;
        #pragma unroll
        for (int c = 0; c < CB; c++)
            TMA3D(sinA[buf] + c * CSZ * 4, &tmap, gc0, gr0, plane + c, mb);
    };
    auto stage_w = [&](int buf) {
        if (wval) cp_async16(swA[buf] + woff, wsrc);
        wsrc += wstep;
    };

    if (tid == 0) stage_in(0, 0);
    stage_w(0);
    CP_COMMIT();

    const int base_off = ty * PITCH + 2 * lx + 3;

    for (int g = 0; g < NG; g++) {
        MBAR_WAIT(mb0 + (g & 1) * 8, (g >> 1) & 1);
        CP_WAIT0();
        __syncthreads();
        if (g + 1 < NG) {
            if (tid == 0) stage_in(g + 1, (g + 1) & 1);
            stage_w((g + 1) & 1);
            CP_COMMIT();
        }
        const int buf = g & 1;

        #pragma unroll
        for (int c = 0; c < CB; c++) {
            const float* sp = &s_in[buf][c * CSZ + base_off];
            const ulonglong2* wq = reinterpret_cast<const ulonglong2*>(&s_w[buf][c * 144]);
            #pragma unroll
            for (int i = 0; i < 3; i++) {
                const float* rp = sp + i * PITCH;
                float xl = rp[0];
                float2 xm = *(const float2*)(rp + 1);
                float xr = rp[3];
                float x[4] = {xl, xm.x, xm.y, xr};
                #pragma unroll
                for (int j = 0; j < 3; j++) {
                    const int t = 3 * i + j;
                    ulonglong2 w0 = wq[4*t], w1 = wq[4*t+1], w2 = wq[4*t+2], w3 = wq[4*t+3];
                    float v0 = x[j]     * k0[t];
                    float v1 = x[j + 1] * k1[t];
                    u64 vv0, vv1;
                    PACK2(vv0, v0, v0);
                    PACK2(vv1, v1, v1);
                    TAP16R(w0, w1, w2, w3, vv0, accA);
                    TAP16R(w0, w1, w2, w3, vv1, accB);
                }
            }
        }
    }

    #pragma unroll
    for (int q = 0; q < 8; q++) {
        int o0 = ocg * 16 + 2 * q;
        float a0, a1, b0v, b1v;
        UNPACK2(a0, a1, accA[q]);
        UNPACK2(b0v, b1v, accB[q]);
        float bias0 = bias[o0], bias1 = bias[o0 + 1];
        float p00 = a0 + bias0, p01 = b0v + bias0;
        float p10 = a1 + bias1, p11 = b1v + bias1;
        p00 = p00 > 0.0f ? p00 : 0.0f;
        p01 = p01 > 0.0f ? p01 : 0.0f;
        p10 = p10 > 0.0f ? p10 : 0.0f;
        p11 = p11 > 0.0f ? p11 : 0.0f;
        *(float2*)&out[((size_t)(b * Co + o0)     * H + oh) * W + ow0] = make_float2(p00, p01);
        *(float2*)&out[((size_t)(b * Co + o0 + 1) * H + oh) * W + ow0] = make_float2(p10, p11);
    }
}

// ─── stride-1, 16x16 images: whole image per block, 1 px/thread, 16 outs ───
// TMA tile 48x18 = 864 floats (3456 B, already a 128B multiple).
__global__ void __launch_bounds__(256) conv_s1_16(
    const __grid_constant__ CUtensorMap tmap, const float* __restrict__ wt,
    const float* __restrict__ bias, const float* __restrict__ kern,
    float* __restrict__ out, int Ci, int Co)
{
    constexpr int CB = 4, PITCH = 48, TSZ = 18 * 48 /*864*/, CSZ = 864;
    __shared__ __align__(128) float s_in[2][CB * CSZ];
    __shared__ __align__(16) float s_w[2][CB * 144];
    __shared__ __align__(8) unsigned long long s_mbar[2];

    const int tid = threadIdx.x;
    const int tx = tid % 16, ty = tid / 16;
    const int ocg = blockIdx.y, b = blockIdx.z;
    const size_t HW = 256;

    const uint32_t mb0 = (uint32_t)__cvta_generic_to_shared(&s_mbar[0]);
    if (tid == 0) { MBAR_INIT(mb0, 1); MBAR_INIT(mb0 + 8, 1); }

    float kreg[9];
    {
        const float* kp = kern + (size_t)b * 9 * HW + (size_t)ty * 16 + tx;
        #pragma unroll
        for (int t = 0; t < 9; t++) kreg[t] = kp[(size_t)t * HW];
    }

    u64 acc[8];
    #pragma unroll
    for (int p = 0; p < 8; p++) acc[p] = 0ull;

    const uint32_t sinA[2] = {(uint32_t)__cvta_generic_to_shared(&s_in[0][0]),
                              (uint32_t)__cvta_generic_to_shared(&s_in[1][0])};
    const uint32_t swA[2]  = {(uint32_t)__cvta_generic_to_shared(&s_w[0][0]),
                              (uint32_t)__cvta_generic_to_shared(&s_w[1][0])};
    const int NG = Ci / CB;

    const bool wval = tid < CB * 36;
    uint32_t woff = 0;
    const float* wsrc = wt;
    {
        int c = tid / 36, rem = tid % 36, ij = rem / 4, q = rem % 4;
        woff = (uint32_t)(c * 144 + ij * 16 + 4 * q) * 4u;
        wsrc = wt + ((size_t)c * 9 + ij) * Co + (size_t)ocg * 16 + 4 * q;
    }
    const size_t wstep = (size_t)CB * 9 * Co;

    __syncthreads();

    auto stage_in = [&](int g, int buf) {
        uint32_t mb = mb0 + buf * 8;
        MBAR_EXPECT(mb, (uint32_t)(CB * TSZ * 4));
        int plane = b * Ci + g * CB;
        #pragma unroll
        for (int c = 0; c < CB; c++)
            TMA3D(sinA[buf] + c * CSZ * 4, &tmap, -4, -1, plane + c, mb);
    };
    auto stage_w = [&](int buf) {
        if (wval) cp_async16(swA[buf] + woff, wsrc);
        wsrc += wstep;
    };

    if (tid == 0) stage_in(0, 0);
    stage_w(0);
    CP_COMMIT();

    const int base_off = ty * PITCH + tx + 3;

    for (int g = 0; g < NG; g++) {
        MBAR_WAIT(mb0 + (g & 1) * 8, (g >> 1) & 1);
        CP_WAIT0();
        __syncthreads();
        if (g + 1 < NG) {
            if (tid == 0) stage_in(g + 1, (g + 1) & 1);
            stage_w((g + 1) & 1);
            CP_COMMIT();
        }
        const int buf = g & 1;

        #pragma unroll
        for (int c = 0; c < CB; c++) {
            const float* sp = &s_in[buf][c * CSZ + base_off];
            const ulonglong2* wq = reinterpret_cast<const ulonglong2*>(&s_w[buf][c * 144]);
            #pragma unroll
            for (int t = 0; t < 9; t++) {
                ulonglong2 w0 = wq[4*t], w1 = wq[4*t+1], w2 = wq[4*t+2], w3 = wq[4*t+3];
                float v = sp[(t / 3) * PITCH + (t % 3)] * kreg[t];
                u64 vv;
                PACK2(vv, v, v);
                TAP16R(w0, w1, w2, w3, vv, acc);
            }
        }
    }

    #pragma unroll
    for (int p = 0; p < 8; p++) {
        int o = ocg * 16 + 2 * p;
        float lo, hi;
        UNPACK2(lo, hi, acc[p]);
        float v0 = lo + bias[o], v1 = hi + bias[o + 1];
        v0 = v0 > 0.0f ? v0 : 0.0f;
        v1 = v1 > 0.0f ? v1 : 0.0f;
        out[((size_t)(b * Co + o)     * 16 + ty) * 16 + tx] = v0;
        out[((size_t)(b * Co + o + 1) * 16 + ty) * 16 + tx] = v1;
    }
}

// ─── stride-2 vertical-pair: output tile 16x32, 2 px/thread, 16 outs (Hout>=32) ───
// TMA tile 40x65 = 2600 floats (10400 B); SMEM channel stride padded to 2624 floats.
__global__ void __launch_bounds__(256) conv_s2v(
    const __grid_constant__ CUtensorMap tmap, const float* __restrict__ wt,
    const float* __restrict__ bias, const float* __restrict__ kern,
    float* __restrict__ out, int Ci, int Co, int H, int W, int tilesX)
{
    constexpr int CB = 2, PITCH = 40, TSZ = 65 * 40 /*2600*/, CSZ = 2624;
    __shared__ __align__(128) float s_in[2][CB * CSZ];
    __shared__ __align__(16) float s_w[2][CB * 144];
    __shared__ __align__(8) unsigned long long s_mbar[2];

    const int tid = threadIdx.x;
    const int tx = tid % 16, ty = tid / 16;
    const int tX = blockIdx.x % tilesX, tY = blockIdx.x / tilesX;
    const int ocg = blockIdx.y, b = blockIdx.z;
    const int Hout = H / 2, Wout = W / 2;
    const int oh0 = tY * 32 + 2 * ty;
    const int ow = tX * 16 + tx;
    const size_t HW = (size_t)H * W;
    const int gr0 = tY * 64 - 1, gc0 = tX * 32 - 4;

    const uint32_t mb0 = (uint32_t)__cvta_generic_to_shared(&s_mbar[0]);
    if (tid == 0) { MBAR_INIT(mb0, 1); MBAR_INIT(mb0 + 8, 1); }

    float kA[9], kB[9];
    if (kern) {
        const float* kp = kern + (size_t)b * 9 * HW + (size_t)(oh0 * 2) * W + ow * 2;
        #pragma unroll
        for (int t = 0; t < 9; t++) {
            kA[t] = kp[(size_t)t * HW];
            kB[t] = kp[(size_t)t * HW + 2 * W];
        }
    } else {
        #pragma unroll
        for (int t = 0; t < 9; t++) { kA[t] = 1.0f; kB[t] = 1.0f; }
    }

    u64 accA[8], accB[8];
    #pragma unroll
    for (int p = 0; p < 8; p++) { accA[p] = 0ull; accB[p] = 0ull; }

    const uint32_t sinA[2] = {(uint32_t)__cvta_generic_to_shared(&s_in[0][0]),
                              (uint32_t)__cvta_generic_to_shared(&s_in[1][0])};
    const uint32_t swA[2]  = {(uint32_t)__cvta_generic_to_shared(&s_w[0][0]),
                              (uint32_t)__cvta_generic_to_shared(&s_w[1][0])};
    const int NG = Ci / CB;

    const bool wval = tid < CB * 36;
    uint32_t woff = 0;
    const float* wsrc = wt;
    {
        int c = tid / 36, rem = tid % 36, ij = rem / 4, q = rem % 4;
        woff = (uint32_t)(c * 144 + ij * 16 + 4 * q) * 4u;
        wsrc = wt + ((size_t)c * 9 + ij) * Co + (size_t)ocg * 16 + 4 * q;
    }
    const size_t wstep = (size_t)CB * 9 * Co;

    __syncthreads();

    auto stage_in = [&](int g, int buf) {
        uint32_t mb = mb0 + buf * 8;
        MBAR_EXPECT(mb, (uint32_t)(CB * TSZ * 4));
        int plane = b * Ci + g * CB;
        #pragma unroll
        for (int c = 0; c < CB; c++)
            TMA3D(sinA[buf] + c * CSZ * 4, &tmap, gc0, gr0, plane + c, mb);
    };
    auto stage_w = [&](int buf) {
        if (wval) cp_async16(swA[buf] + woff, wsrc);
        wsrc += wstep;
    };

    if (tid == 0) stage_in(0, 0);
    stage_w(0);
    CP_COMMIT();

    const int base_off = (4 * ty) * PITCH + 2 * tx + 3;

    for (int g = 0; g < NG; g++) {
        MBAR_WAIT(mb0 + (g & 1) * 8, (g >> 1) & 1);
        CP_WAIT0();
        __syncthreads();
        if (g + 1 < NG) {
            if (tid == 0) stage_in(g + 1, (g + 1) & 1);
            stage_w((g + 1) & 1);
            CP_COMMIT();
        }
        const int buf = g & 1;

        #pragma unroll
        for (int c = 0; c < CB; c++) {
            const float* sp = &s_in[buf][c * CSZ + base_off];
            float x[5][3];
            #pragma unroll
            for (int r = 0; r < 5; r++) {
                const float* rp = sp + r * PITCH;
                x[r][0] = rp[0]; x[r][1] = rp[1]; x[r][2] = rp[2];
            }
            const ulonglong2* wq = reinterpret_cast<const ulonglong2*>(&s_w[buf][c * 144]);
            #pragma unroll
            for (int i = 0; i < 3; i++)
            #pragma unroll
            for (int j = 0; j < 3; j++) {
                const int t = 3 * i + j;
                ulonglong2 w0 = wq[4*t], w1 = wq[4*t+1], w2 = wq[4*t+2], w3 = wq[4*t+3];
                float vA = x[i][j]     * kA[t];
                float vB = x[i + 2][j] * kB[t];
                u64 vvA, vvB;
                PACK2(vvA, vA, vA);
                PACK2(vvB, vB, vB);
                TAP16R(w0, w1, w2, w3, vvA, accA);
                TAP16R(w0, w1, w2, w3, vvB, accB);
            }
        }
    }

    #pragma unroll
    for (int p = 0; p < 8; p++) {
        int o = ocg * 16 + 2 * p;
        float a0, a1, b0v, b1v;
        UNPACK2(a0, a1, accA[p]);
        UNPACK2(b0v, b1v, accB[p]);
        float bias0 = bias[o], bias1 = bias[o + 1];
        float p00 = a0 + bias0, p01 = b0v + bias0;
        float p10 = a1 + bias1, p11 = b1v + bias1;
        p00 = p00 > 0.0f ? p00 : 0.0f;
        p01 = p01 > 0.0f ? p01 : 0.0f;
        p10 = p10 > 0.0f ? p10 : 0.0f;
        p11 = p11 > 0.0f ? p11 : 0.0f;
        float* o0p = &out[((size_t)(b * Co + o)     * Hout + oh0) * Wout + ow];
        float* o1p = &out[((size_t)(b * Co + o + 1) * Hout + oh0) * Wout + ow];
        o0p[0] = p00; o0p[Wout] = p01;
        o1p[0] = p10; o1p[Wout] = p11;
    }
}

// ─── stride-2 small (Hout<32): 16x16 output tile, 1 px/thread, 16 outputs ───
// TMA tile 40x33 = 1320 floats (5280 B); SMEM channel stride padded to 1344 floats.
__global__ void __launch_bounds__(256) conv_s2(
    const __grid_constant__ CUtensorMap tmap, const float* __restrict__ wt,
    const float* __restrict__ bias, const float* __restrict__ kern,
    float* __restrict__ out, int Ci, int Co, int H, int W, int tilesX)
{
    constexpr int CB = 2, PITCH = 40, TSZ = 33 * 40 /*1320*/, CSZ = 1344;
    __shared__ __align__(128) float s_in[2][CB * CSZ];
    __shared__ __align__(16) float s_w[2][CB * 144];
    __shared__ __align__(8) unsigned long long s_mbar[2];

    const int tid = threadIdx.x;
    const int tx = tid % 16, ty = tid / 16;
    const int tX = blockIdx.x % tilesX, tY = blockIdx.x / tilesX;
    const int ocg = blockIdx.y, b = blockIdx.z;
    const int Hout = H / 2, Wout = W / 2;
    const int oh = tY * 16 + ty, ow = tX * 16 + tx;
    const size_t HW = (size_t)H * W;
    const int gr0 = tY * 32 - 1, gc0 = tX * 32 - 4;

    const uint32_t mb0 = (uint32_t)__cvta_generic_to_shared(&s_mbar[0]);
    if (tid == 0) { MBAR_INIT(mb0, 1); MBAR_INIT(mb0 + 8, 1); }

    float kreg[9];
    if (kern) {
        const float* kp = kern + (size_t)b * 9 * HW + (size_t)(oh * 2) * W + ow * 2;
        #pragma unroll
        for (int t = 0; t < 9; t++) kreg[t] = kp[(size_t)t * HW];
    } else {
        #pragma unroll
        for (int t = 0; t < 9; t++) kreg[t] = 1.0f;
    }

    u64 acc[8];
    #pragma unroll
    for (int p = 0; p < 8; p++) acc[p] = 0ull;

    const uint32_t sinA[2] = {(uint32_t)__cvta_generic_to_shared(&s_in[0][0]),
                              (uint32_t)__cvta_generic_to_shared(&s_in[1][0])};
    const uint32_t swA[2]  = {(uint32_t)__cvta_generic_to_shared(&s_w[0][0]),
                              (uint32_t)__cvta_generic_to_shared(&s_w[1][0])};
    const int NG = Ci / CB;

    const bool wval = tid < CB * 36;
    uint32_t woff = 0;
    const float* wsrc = wt;
    {
        int c = tid / 36, rem = tid % 36, ij = rem / 4, q = rem % 4;
        woff = (uint32_t)(c * 144 + ij * 16 + 4 * q) * 4u;
        wsrc = wt + ((size_t)c * 9 + ij) * Co + (size_t)ocg * 16 + 4 * q;
    }
    const size_t wstep = (size_t)CB * 9 * Co;

    __syncthreads();

    auto stage_in = [&](int g, int buf) {
        uint32_t mb = mb0 + buf * 8;
        MBAR_EXPECT(mb, (uint32_t)(CB * TSZ * 4));
        int plane = b * Ci + g * CB;
        #pragma unroll
        for (int c = 0; c < CB; c++)
            TMA3D(sinA[buf] + c * CSZ * 4, &tmap, gc0, gr0, plane + c, mb);
    };
    auto stage_w = [&](int buf) {
        if (wval) cp_async16(swA[buf] + woff, wsrc);
        wsrc += wstep;
    };

    if (tid == 0) stage_in(0, 0);
    stage_w(0);
    CP_COMMIT();

    const int base_off = (2 * ty) * PITCH + 2 * tx + 3;

    for (int g = 0; g < NG; g++) {
        MBAR_WAIT(mb0 + (g & 1) * 8, (g >> 1) & 1);
        CP_WAIT0();
        __syncthreads();
        if (g + 1 < NG) {
            if (tid == 0) stage_in(g + 1, (g + 1) & 1);
            stage_w((g + 1) & 1);
            CP_COMMIT();
        }
        const int buf = g & 1;

        #pragma unroll
        for (int c = 0; c < CB; c++) {
            const float* sp = &s_in[buf][c * CSZ + base_off];
            const ulonglong2* wq = reinterpret_cast<const ulonglong2*>(&s_w[buf][c * 144]);
            #pragma unroll
            for (int t = 0; t < 9; t++) {
                ulonglong2 w0 = wq[4*t], w1 = wq[4*t+1], w2 = wq[4*t+2], w3 = wq[4*t+3];
                float v = sp[(t / 3) * PITCH + (t % 3)] * kreg[t];
                u64 vv;
                PACK2(vv, v, v);
                TAP16R(w0, w1, w2, w3, vv, acc);
            }
        }
    }

    #pragma unroll
    for (int p = 0; p < 8; p++) {
        int o = ocg * 16 + 2 * p;
        float lo, hi;
        UNPACK2(lo, hi, acc[p]);
        float v0 = lo + bias[o], v1 = hi + bias[o + 1];
        v0 = v0 > 0.0f ? v0 : 0.0f;
        v1 = v1 > 0.0f ? v1 : 0.0f;
        out[((size_t)(b * Co + o)     * Hout + oh) * Wout + ow] = v0;
        out[((size_t)(b * Co + o + 1) * Hout + oh) * Wout + ow] = v1;
    }
}

__global__ void pac_gauss_kernel(const float* __restrict__ f, float* __restrict__ out,
                                 int C, int H, int W, float coeff2)
{
    const int b = blockIdx.z;
    const int idx = blockIdx.x * blockDim.x + threadIdx.x;
    if (idx >= H * W) return;
    const int h = idx / W, w = idx % W;

    float acc[9];
    #pragma unroll
    for (int t = 0; t < 9; t++) acc[t] = 0.0f;

    const float* fb = f + (size_t)b * C * H * W;
    for (int c = 0; c < C; c++) {
        const float* fc = fb + (size_t)c * H * W;
        float ctr = fc[idx];
        #pragma unroll
        for (int i = 0; i < 3; i++)
        #pragma unroll
        for (int j = 0; j < 3; j++) {
            int hh = h + i - 1, ww = w + j - 1;
            float nb = (hh >= 0 && hh < H && ww >= 0 && ww < W) ? fc[hh * W + ww] : 0.0f;
            float d = nb - ctr;
            acc[i * 3 + j] += d * d;
        }
    }

    float* ob = out + (size_t)b * 9 * H * W;
    #pragma unroll
    for (int t = 0; t < 9; t++)
        ob[(size_t)t * H * W + idx] = expf(-0.5f * coeff2 * acc[t]);
}

// ─── host side ───

typedef CUresult (CUDAAPI *PFN_encode)(
    CUtensorMap*, CUtensorMapDataType, cuuint32_t, void*,
    const cuuint64_t*, const cuuint64_t*, const cuuint32_t*, const cuuint32_t*,
    CUtensorMapInterleave, CUtensorMapSwizzle, CUtensorMapL2promotion,
    CUtensorMapFloatOOBfill);

static CUtensorMap h_maps[14];

static void make_map(PFN_encode enc, CUtensorMap* m, const void* base,
                     int W, int H, int planes, int boxw, int boxh)
{
    cuuint64_t dims[3] = {(cuuint64_t)W, (cuuint64_t)H, (cuuint64_t)planes};
    cuuint64_t strides[2] = {(cuuint64_t)W * 4, (cuuint64_t)W * H * 4};
    cuuint32_t box[3] = {(cuuint32_t)boxw, (cuuint32_t)boxh, 1};
    cuuint32_t es[3] = {1, 1, 1};
    enc(m, CU_TENSOR_MAP_DATA_TYPE_FLOAT32, 3, const_cast<void*>(base),
        dims, strides, box, es,
        CU_TENSOR_MAP_INTERLEAVE_NONE, CU_TENSOR_MAP_SWIZZLE_NONE,
        CU_TENSOR_MAP_L2_PROMOTION_L2_128B, CU_TENSOR_MAP_FLOAT_OOB_FILL_NONE);
}

static void conv_s1_l(const CUtensorMap& m, const float* wt, const float* b,
                      const float* kern, float* out, int Ci, int Co, int H, int W)
{
    if (W >= 32) {
        int tilesX = W / 32;
        dim3 grid(tilesX * (H / 16), Co / 16, 2);
        if (Ci % 4 == 0)
            conv_s1<4><<<grid, 256>>>(m, wt, b, kern, out, Ci, Co, H, W, tilesX);
        else
            conv_s1<1><<<grid, 256>>>(m, wt, b, kern, out, Ci, Co, H, W, tilesX);
    } else {
        dim3 grid(1, Co / 16, 2);
        conv_s1_16<<<grid, 256>>>(m, wt, b, kern, out, Ci, Co);
    }
}

static void conv_s2_l(const CUtensorMap& m, const float* wt, const float* b,
                      const float* kern, float* out, int Ci, int Co, int H, int W)
{
    int Hout = H / 2, Wout = W / 2;
    if (Hout >= 32) {
        int tilesX = Wout / 16;
        dim3 grid(tilesX * (Hout / 32), Co / 16, 2);
        conv_s2v<<<grid, 256>>>(m, wt, b, kern, out, Ci, Co, H, W, tilesX);
    } else {
        int tilesX = W / 32;
        dim3 grid(tilesX * (H / 32), Co / 16, 2);
        conv_s2<<<grid, 256>>>(m, wt, b, kern, out, Ci, Co, H, W, tilesX);
    }
}

static void pac_layer(const float* f, float* out, int C, int H, int W, float coeff2)
{
    int hw = H * W;
    dim3 grid((hw + 255) / 256, 1, 2);
    pac_gauss_kernel<<<grid, 256>>>(f, out, C, H, W, coeff2);
}

extern "C" void kernel_launch(void* const* d_in, const int* in_sizes, int n_in,
                              void* d_out, int out_size)
{
    const float* x = (const float*)d_in[0];
    WPtrs wp;
    const float* B14[14];
    for (int i = 0; i < 14; i++) {
        wp.p[i] = (const float*)d_in[1 + 2 * i];
        B14[i]  = (const float*)d_in[2 + 2 * i];
    }

    float* bufA; float* bufB; float* wT;
    cudaGetSymbolAddress((void**)&bufA, g_bufA);
    cudaGetSymbolAddress((void**)&bufB, g_bufB);
    cudaGetSymbolAddress((void**)&wT,  g_wT);

    static const size_t OFF[15] = {0,576,37440,74304,148032,295488,442944,737856,1327680,
                                   1917504,3097152,5456448,7815744,12534336,21971520};
    const float* wt[14];
    for (int l = 0; l < 14; l++) wt[l] = wT + OFF[l];

    float* out = (float*)d_out;
    float* h1 = out;
    float* h2 = h1 + 8388608;
    float* h3 = h2 + 4194304;
    float* h4 = h3 + 2097152;
    float* h5 = h4 + 1048576;
    float* k2 = h5 + 524288;
    float* k3 = k2 + 294912;
    float* k4 = k3 + 73728;
    float* k5 = k4 + 18432;

    // Encode tensormaps (host-side, capture-time only)
    PFN_encode enc = nullptr;
    cudaDriverEntryPointQueryResult qres;
#if CUDART_VERSION >= 12050
    cudaGetDriverEntryPointByVersion("cuTensorMapEncodeTiled", (void**)&enc, 12000,
                                     cudaEnableDefault, &qres);
#else
    cudaGetDriverEntryPoint("cuTensorMapEncodeTiled", (void**)&enc,
                            cudaEnableDefault, &qres);
#endif
    make_map(enc, &h_maps[0],  x,    256, 256, 2,    40, 18);  // c11 s1
    make_map(enc, &h_maps[1],  bufA, 256, 256, 128,  40, 18);  // c12 s1
    make_map(enc, &h_maps[2],  h1,   256, 256, 128,  40, 65);  // c13 s2v
    make_map(enc, &h_maps[3],  bufA, 128, 128, 128,  40, 18);  // c21 s1
    make_map(enc, &h_maps[4],  bufB, 128, 128, 256,  40, 18);  // c22 s1
    make_map(enc, &h_maps[5],  h2,   128, 128, 256,  40, 65);  // c23 s2v
    make_map(enc, &h_maps[6],  bufA, 64, 64, 256,    40, 18);  // c31 s1
    make_map(enc, &h_maps[7],  bufB, 64, 64, 512,    40, 18);  // c32 s1
    make_map(enc, &h_maps[8],  h3,   64, 64, 512,    40, 65);  // c33 s2v
    make_map(enc, &h_maps[9],  bufA, 32, 32, 512,    40, 18);  // c41 s1
    make_map(enc, &h_maps[10], bufB, 32, 32, 1024,   40, 18);  // c42 s1
    make_map(enc, &h_maps[11], h4,   32, 32, 1024,   40, 33);  // c43 s2
    make_map(enc, &h_maps[12], bufA, 16, 16, 1024,   48, 18);  // c51 s1_16
    make_map(enc, &h_maps[13], bufB, 16, 16, 2048,   48, 18);  // c52 s1_16

    transpose_all_kernel<<<(21971520 + 255) / 256, 256>>>(wp, wT);

    const float KC2 = 1e-4f * 1e-4f;

    // Stage 1
    conv_s1_l(h_maps[0], wt[0], B14[0], nullptr, bufA, 1,  64, 256, 256);
    conv_s1_l(h_maps[1], wt[1], B14[1], nullptr, h1,   64, 64, 256, 256);
    conv_s2_l(h_maps[2], wt[2], B14[2], nullptr, bufA, 64, 64, 256, 256); // -> 2,64,128,128

    // Stage 2
    pac_layer(bufA, k2, 64, 128, 128, KC2);
    conv_s1_l(h_maps[3], wt[3], B14[3], k2, bufB, 64,  128, 128, 128);
    conv_s1_l(h_maps[4], wt[4], B14[4], k2, h2,   128, 128, 128, 128);
    conv_s2_l(h_maps[5], wt[5], B14[5], k2, bufA, 128, 128, 128, 128);    // -> 2,128,64,64

    // Stage 3
    pac_layer(bufA, k3, 128, 64, 64, KC2);
    conv_s1_l(h_maps[6], wt[6], B14[6], k3, bufB, 128, 256, 64, 64);
    conv_s1_l(h_maps[7], wt[7], B14[7], k3, h3,   256, 256, 64, 64);
    conv_s2_l(h_maps[8], wt[8], B14[8], k3, bufA, 256, 256, 64, 64);      // -> 2,256,32,32

    // Stage 4 (guidance h4*2 -> coeff^2 = 4)
    pac_layer(bufA, k4, 256, 32, 32, 4.0f);
    conv_s1_l(h_maps[9],  wt[9],  B14[9],  k4, bufB, 256, 512, 32, 32);
    conv_s1_l(h_maps[10], wt[10], B14[10], k4, h4,   512, 512, 32, 32);
    conv_s2_l(h_maps[11], wt[11], B14[11], k4, bufA, 512, 512, 32, 32);   // -> 2,512,16,16

    // Stage 5
    pac_layer(bufA, k5, 512, 16, 16, KC2);
    conv_s1_l(h_maps[12], wt[12], B14[12], k5, bufB, 512,  1024, 16, 16);
    conv_s1_l(h_maps[13], wt[13], B14[13], k5, h5,   1024, 1024, 16, 16);
}

// round 12
// speedup vs baseline: 1.0896x; 1.0896x over previous
#include <cuda.h>
#include <cuda_runtime.h>
#include <cstdint>

typedef unsigned long long u64;

__device__ __align__(256) float g_bufA[8388608];
__device__ __align__(256) float g_bufB[4194304];
__device__ __align__(256) float g_wT [21971520];   // transposed weights [c][ij][o]
__device__ __align__(256) float g_part[4194304];   // split-K partial sums

__device__ __forceinline__ void cp_async16(uint32_t saddr, const float* gptr) {
    asm volatile("cp.async.cg.shared.global [%0], [%1], 16;" :: "r"(saddr), "l"(gptr));
}
#define CP_COMMIT() asm volatile("cp.async.commit_group;" ::: "memory")
#define CP_WAIT0()  asm volatile("cp.async.wait_group 0;" ::: "memory")
#define FFMA2(acc, w, v) asm("fma.rn.f32x2 %0, %1, %2, %0;" : "+l"(acc) : "l"(w), "l"(v))
#define PACK2(d, a, b)   asm("mov.b64 %0, {%1, %2};" : "=l"(d) : "f"(a), "f"(b))
#define UNPACK2(lo, hi, p) asm("mov.b64 {%0, %1}, %2;" : "=f"(lo), "=f"(hi) : "l"(p))

#define MBAR_INIT(mbar, cnt) \
    asm volatile("mbarrier.init.shared.b64 [%0], %1;" :: "r"(mbar), "r"(cnt) : "memory")
#define MBAR_EXPECT(mbar, bytes) \
    asm volatile("mbarrier.arrive.expect_tx.shared.b64 _, [%0], %1;" :: "r"(mbar), "r"(bytes) : "memory")
#define MBAR_WAIT(mbar, par) do { \
    asm volatile( \
        "{\n\t.reg .pred P1;\n\t" \
        "WAIT_LOOP_%=:\n\t" \
        "mbarrier.try_wait.parity.acquire.cta.shared::cta.b64 P1, [%0], %1, 0x989680;\n\t" \
        "@P1 bra.uni WAIT_DONE_%=;\n\t" \
        "bra.uni WAIT_LOOP_%=;\n\t" \
        "WAIT_DONE_%=:\n\t}" \
        :: "r"(mbar), "r"(par) : "memory"); \
} while(0)
#define TMA3D(dst, tmapp, cx, cy, cz, mbar) \
    asm volatile("cp.async.bulk.tensor.3d.shared::cta.global.tile.mbarrier::complete_tx::bytes " \
        "[%0], [%1, {%2, %3, %4}], [%5];" \
        :: "r"(dst), "l"(tmapp), "r"(cx), "r"(cy), "r"(cz), "r"(mbar) : "memory")

// ─── fused weight transpose: one launch for all 14 layers ───
struct WPtrs { const float* p[14]; };

__global__ void transpose_all_kernel(WPtrs wp, float* __restrict__ wt)
{
    const int i = blockIdx.x * 256 + threadIdx.x;
    if (i >= 21971520) return;
    const int CiA[14] = {1,64,64, 64,128,128, 128,256,256, 256,512,512, 512,1024};
    const int CoA[14] = {64,64,64, 128,128,128, 256,256,256, 512,512,512, 1024,1024};
    const int OFF[15] = {0,576,37440,74304,148032,295488,442944,737856,1327680,
                         1917504,3097152,5456448,7815744,12534336,21971520};
    int l = 0;
    #pragma unroll
    for (int k = 1; k < 14; k++) if (i >= OFF[k]) l = k;
    int j = i - OFF[l];
    int Co = CoA[l], Ci = CiA[l];
    int o = j % Co;
    int cij = j / Co;
    int c = cij / 9, ij = cij % 9;
    wt[i] = wp.p[l][((size_t)o * Ci + c) * 9 + ij];
}

// split-K reduction: out = relu(bias + sum_s part[s])
__global__ void reduce_brelu(const float* __restrict__ part, const float* __restrict__ bias,
                             float* __restrict__ out, int Co, int HW, int S, int tot)
{
    int idx = blockIdx.x * 256 + threadIdx.x;
    if (idx >= tot) return;
    int o = (idx / HW) % Co;
    float v = bias[o];
    for (int s = 0; s < S; s++) v += part[(size_t)s * tot + idx];
    out[idx] = v > 0.0f ? v : 0.0f;
}

#define TAP16R(w0, w1, w2, w3, vv, A)                                  \
    {                                                                  \
        FFMA2((A)[0], (w0).x, vv); FFMA2((A)[1], (w0).y, vv);          \
        FFMA2((A)[2], (w1).x, vv); FFMA2((A)[3], (w1).y, vv);          \
        FFMA2((A)[4], (w2).x, vv); FFMA2((A)[5], (w2).y, vv);          \
        FFMA2((A)[6], (w3).x, vv); FFMA2((A)[7], (w3).y, vv);          \
    }

// ─── stride-1, wide images (W>=32): 32x16 tile, 2 px/thread, 16 outs ───
template<int CB>
__global__ void __launch_bounds__(256) conv_s1(
    const __grid_constant__ CUtensorMap tmap, const float* __restrict__ wt,
    const float* __restrict__ bias, const float* __restrict__ kern,
    float* __restrict__ out, int Ci, int Co, int H, int W, int tilesX,
    int Csub, int S)
{
    constexpr int PITCH = 40, TSZ = 18 * 40, CSZ = 736;
    __shared__ __align__(128) float s_in[2][CB * CSZ];
    __shared__ __align__(16) float s_w[2][CB * 144];
    __shared__ __align__(8) unsigned long long s_mbar[2];

    const int tid = threadIdx.x;
    const int lx = tid % 16, ty = tid / 16;
    const int tX = blockIdx.x % tilesX, tY = blockIdx.x / tilesX;
    const int ocg = blockIdx.y;
    const int zz = blockIdx.z;
    const int b = zz & 1, sk = zz >> 1;
    const int cbase = sk * Csub;
    const int oh = tY * 16 + ty, ow0 = tX * 32 + 2 * lx;
    const size_t HW = (size_t)H * W;
    const int gr0 = tY * 16 - 1, gc0 = tX * 32 - 4;

    const uint32_t mb0 = (uint32_t)__cvta_generic_to_shared(&s_mbar[0]);
    if (tid == 0) { MBAR_INIT(mb0, 1); MBAR_INIT(mb0 + 8, 1); }

    float k0[9], k1[9];
    if (kern) {
        const float* kp = kern + (size_t)b * 9 * HW + (size_t)oh * W + ow0;
        #pragma unroll
        for (int t = 0; t < 9; t++) {
            float2 kk = *(const float2*)(kp + (size_t)t * HW);
            k0[t] = kk.x; k1[t] = kk.y;
        }
    } else {
        #pragma unroll
        for (int t = 0; t < 9; t++) { k0[t] = 1.0f; k1[t] = 1.0f; }
    }

    u64 accA[8], accB[8];
    #pragma unroll
    for (int p = 0; p < 8; p++) { accA[p] = 0ull; accB[p] = 0ull; }

    const uint32_t sinA[2] = {(uint32_t)__cvta_generic_to_shared(&s_in[0][0]),
                              (uint32_t)__cvta_generic_to_shared(&s_in[1][0])};
    const uint32_t swA[2]  = {(uint32_t)__cvta_generic_to_shared(&s_w[0][0]),
                              (uint32_t)__cvta_generic_to_shared(&s_w[1][0])};
    const int NG = Csub / CB;

    const bool wval = tid < CB * 36;
    uint32_t woff = 0;
    const float* wsrc = wt;
    {
        int c = tid / 36, rem = tid % 36, ij = rem / 4, q = rem % 4;
        woff = (uint32_t)(c * 144 + ij * 16 + 4 * q) * 4u;
        wsrc = wt + ((size_t)(cbase + c) * 9 + ij) * Co + (size_t)ocg * 16 + 4 * q;
    }
    const size_t wstep = (size_t)CB * 9 * Co;

    __syncthreads();

    auto stage_in = [&](int g, int buf) {
        uint32_t mb = mb0 + buf * 8;
        MBAR_EXPECT(mb, (uint32_t)(CB * TSZ * 4));
        int plane = b * Ci + cbase + g * CB;
        #pragma unroll
        for (int c = 0; c < CB; c++)
            TMA3D(sinA[buf] + c * CSZ * 4, &tmap, gc0, gr0, plane + c, mb);
    };
    auto stage_w = [&](int buf) {
        if (wval) cp_async16(swA[buf] + woff, wsrc);
        wsrc += wstep;
    };

    if (tid == 0) stage_in(0, 0);
    stage_w(0);
    CP_COMMIT();

    const int base_off = ty * PITCH + 2 * lx + 3;

    for (int g = 0; g < NG; g++) {
        MBAR_WAIT(mb0 + (g & 1) * 8, (g >> 1) & 1);
        CP_WAIT0();
        __syncthreads();
        if (g + 1 < NG) {
            if (tid == 0) stage_in(g + 1, (g + 1) & 1);
            stage_w((g + 1) & 1);
            CP_COMMIT();
        }
        const int buf = g & 1;

        #pragma unroll
        for (int c = 0; c < CB; c++) {
            const float* sp = &s_in[buf][c * CSZ + base_off];
            const ulonglong2* wq = reinterpret_cast<const ulonglong2*>(&s_w[buf][c * 144]);
            #pragma unroll
            for (int i = 0; i < 3; i++) {
                const float* rp = sp + i * PITCH;
                float xl = rp[0];
                float2 xm = *(const float2*)(rp + 1);
                float xr = rp[3];
                float x[4] = {xl, xm.x, xm.y, xr};
                #pragma unroll
                for (int j = 0; j < 3; j++) {
                    const int t = 3 * i + j;
                    ulonglong2 w0 = wq[4*t], w1 = wq[4*t+1], w2 = wq[4*t+2], w3 = wq[4*t+3];
                    float v0 = x[j]     * k0[t];
                    float v1 = x[j + 1] * k1[t];
                    u64 vv0, vv1;
                    PACK2(vv0, v0, v0);
                    PACK2(vv1, v1, v1);
                    TAP16R(w0, w1, w2, w3, vv0, accA);
                    TAP16R(w0, w1, w2, w3, vv1, accB);
                }
            }
        }
    }

    if (S == 1) {
        #pragma unroll
        for (int q = 0; q < 8; q++) {
            int o0 = ocg * 16 + 2 * q;
            float a0, a1, b0v, b1v;
            UNPACK2(a0, a1, accA[q]);
            UNPACK2(b0v, b1v, accB[q]);
            float bias0 = bias[o0], bias1 = bias[o0 + 1];
            float p00 = a0 + bias0, p01 = b0v + bias0;
            float p10 = a1 + bias1, p11 = b1v + bias1;
            p00 = p00 > 0.0f ? p00 : 0.0f;
            p01 = p01 > 0.0f ? p01 : 0.0f;
            p10 = p10 > 0.0f ? p10 : 0.0f;
            p11 = p11 > 0.0f ? p11 : 0.0f;
            *(float2*)&out[((size_t)(b * Co + o0)     * H + oh) * W + ow0] = make_float2(p00, p01);
            *(float2*)&out[((size_t)(b * Co + o0 + 1) * H + oh) * W + ow0] = make_float2(p10, p11);
        }
    } else {
        float* pp = out + (size_t)sk * 2 * Co * HW;
        #pragma unroll
        for (int q = 0; q < 8; q++) {
            int o0 = ocg * 16 + 2 * q;
            float a0, a1, b0v, b1v;
            UNPACK2(a0, a1, accA[q]);
            UNPACK2(b0v, b1v, accB[q]);
            *(float2*)&pp[((size_t)(b * Co + o0)     * H + oh) * W + ow0] = make_float2(a0, b0v);
            *(float2*)&pp[((size_t)(b * Co + o0 + 1) * H + oh) * W + ow0] = make_float2(a1, b1v);
        }
    }
}

// ─── stride-1, 16x16 images: whole image per block, 1 px/thread, 16 outs ───
__global__ void __launch_bounds__(256) conv_s1_16(
    const __grid_constant__ CUtensorMap tmap, const float* __restrict__ wt,
    const float* __restrict__ bias, const float* __restrict__ kern,
    float* __restrict__ out, int Ci, int Co, int Csub, int S)
{
    constexpr int CB = 4, PITCH = 48, TSZ = 18 * 48, CSZ = 864;
    __shared__ __align__(128) float s_in[2][CB * CSZ];
    __shared__ __align__(16) float s_w[2][CB * 144];
    __shared__ __align__(8) unsigned long long s_mbar[2];

    const int tid = threadIdx.x;
    const int tx = tid % 16, ty = tid / 16;
    const int ocg = blockIdx.y;
    const int zz = blockIdx.z;
    const int b = zz & 1, sk = zz >> 1;
    const int cbase = sk * Csub;
    const size_t HW = 256;

    const uint32_t mb0 = (uint32_t)__cvta_generic_to_shared(&s_mbar[0]);
    if (tid == 0) { MBAR_INIT(mb0, 1); MBAR_INIT(mb0 + 8, 1); }

    float kreg[9];
    {
        const float* kp = kern + (size_t)b * 9 * HW + (size_t)ty * 16 + tx;
        #pragma unroll
        for (int t = 0; t < 9; t++) kreg[t] = kp[(size_t)t * HW];
    }

    u64 acc[8];
    #pragma unroll
    for (int p = 0; p < 8; p++) acc[p] = 0ull;

    const uint32_t sinA[2] = {(uint32_t)__cvta_generic_to_shared(&s_in[0][0]),
                              (uint32_t)__cvta_generic_to_shared(&s_in[1][0])};
    const uint32_t swA[2]  = {(uint32_t)__cvta_generic_to_shared(&s_w[0][0]),
                              (uint32_t)__cvta_generic_to_shared(&s_w[1][0])};
    const int NG = Csub / CB;

    const bool wval = tid < CB * 36;
    uint32_t woff = 0;
    const float* wsrc = wt;
    {
        int c = tid / 36, rem = tid % 36, ij = rem / 4, q = rem % 4;
        woff = (uint32_t)(c * 144 + ij * 16 + 4 * q) * 4u;
        wsrc = wt + ((size_t)(cbase + c) * 9 + ij) * Co + (size_t)ocg * 16 + 4 * q;
    }
    const size_t wstep = (size_t)CB * 9 * Co;

    __syncthreads();

    auto stage_in = [&](int g, int buf) {
        uint32_t mb = mb0 + buf * 8;
        MBAR_EXPECT(mb, (uint32_t)(CB * TSZ * 4));
        int plane = b * Ci + cbase + g * CB;
        #pragma unroll
        for (int c = 0; c < CB; c++)
            TMA3D(sinA[buf] + c * CSZ * 4, &tmap, -4, -1, plane + c, mb);
    };
    auto stage_w = [&](int buf) {
        if (wval) cp_async16(swA[buf] + woff, wsrc);
        wsrc += wstep;
    };

    if (tid == 0) stage_in(0, 0);
    stage_w(0);
    CP_COMMIT();

    const int base_off = ty * PITCH + tx + 3;

    for (int g = 0; g < NG; g++) {
        MBAR_WAIT(mb0 + (g & 1) * 8, (g >> 1) & 1);
        CP_WAIT0();
        __syncthreads();
        if (g + 1 < NG) {
            if (tid == 0) stage_in(g + 1, (g + 1) & 1);
            stage_w((g + 1) & 1);
            CP_COMMIT();
        }
        const int buf = g & 1;

        #pragma unroll
        for (int c = 0; c < CB; c++) {
            const float* sp = &s_in[buf][c * CSZ + base_off];
            const ulonglong2* wq = reinterpret_cast<const ulonglong2*>(&s_w[buf][c * 144]);
            #pragma unroll
            for (int t = 0; t < 9; t++) {
                ulonglong2 w0 = wq[4*t], w1 = wq[4*t+1], w2 = wq[4*t+2], w3 = wq[4*t+3];
                float v = sp[(t / 3) * PITCH + (t % 3)] * kreg[t];
                u64 vv;
                PACK2(vv, v, v);
                TAP16R(w0, w1, w2, w3, vv, acc);
            }
        }
    }

    if (S == 1) {
        #pragma unroll
        for (int p = 0; p < 8; p++) {
            int o = ocg * 16 + 2 * p;
            float lo, hi;
            UNPACK2(lo, hi, acc[p]);
            float v0 = lo + bias[o], v1 = hi + bias[o + 1];
            v0 = v0 > 0.0f ? v0 : 0.0f;
            v1 = v1 > 0.0f ? v1 : 0.0f;
            out[((size_t)(b * Co + o)     * 16 + ty) * 16 + tx] = v0;
            out[((size_t)(b * Co + o + 1) * 16 + ty) * 16 + tx] = v1;
        }
    } else {
        float* pp = out + (size_t)sk * 2 * Co * HW;
        #pragma unroll
        for (int p = 0; p < 8; p++) {
            int o = ocg * 16 + 2 * p;
            float lo, hi;
            UNPACK2(lo, hi, acc[p]);
            pp[((size_t)(b * Co + o)     * 16 + ty) * 16 + tx] = lo;
            pp[((size_t)(b * Co + o + 1) * 16 + ty) * 16 + tx] = hi;
        }
    }
}

// ─── stride-2 vertical-pair: output tile 16x32, 2 px/thread, 16 outs (Hout>=32) ───
__global__ void __launch_bounds__(256) conv_s2v(
    const __grid_constant__ CUtensorMap tmap, const float* __restrict__ wt,
    const float* __restrict__ bias, const float* __restrict__ kern,
    float* __restrict__ out, int Ci, int Co, int H, int W, int tilesX,
    int Csub, int S)
{
    constexpr int CB = 2, PITCH = 40, TSZ = 65 * 40, CSZ = 2624;
    __shared__ __align__(128) float s_in[2][CB * CSZ];
    __shared__ __align__(16) float s_w[2][CB * 144];
    __shared__ __align__(8) unsigned long long s_mbar[2];

    const int tid = threadIdx.x;
    const int tx = tid % 16, ty = tid / 16;
    const int tX = blockIdx.x % tilesX, tY = blockIdx.x / tilesX;
    const int ocg = blockIdx.y;
    const int zz = blockIdx.z;
    const int b = zz & 1, sk = zz >> 1;
    const int cbase = sk * Csub;
    const int Hout = H / 2, Wout = W / 2;
    const int oh0 = tY * 32 + 2 * ty;
    const int ow = tX * 16 + tx;
    const size_t HW = (size_t)H * W;
    const int gr0 = tY * 64 - 1, gc0 = tX * 32 - 4;

    const uint32_t mb0 = (uint32_t)__cvta_generic_to_shared(&s_mbar[0]);
    if (tid == 0) { MBAR_INIT(mb0, 1); MBAR_INIT(mb0 + 8, 1); }

    float kA[9], kB[9];
    if (kern) {
        const float* kp = kern + (size_t)b * 9 * HW + (size_t)(oh0 * 2) * W + ow * 2;
        #pragma unroll
        for (int t = 0; t < 9; t++) {
            kA[t] = kp[(size_t)t * HW];
            kB[t] = kp[(size_t)t * HW + 2 * W];
        }
    } else {
        #pragma unroll
        for (int t = 0; t < 9; t++) { kA[t] = 1.0f; kB[t] = 1.0f; }
    }

    u64 accA[8], accB[8];
    #pragma unroll
    for (int p = 0; p < 8; p++) { accA[p] = 0ull; accB[p] = 0ull; }

    const uint32_t sinA[2] = {(uint32_t)__cvta_generic_to_shared(&s_in[0][0]),
                              (uint32_t)__cvta_generic_to_shared(&s_in[1][0])};
    const uint32_t swA[2]  = {(uint32_t)__cvta_generic_to_shared(&s_w[0][0]),
                              (uint32_t)__cvta_generic_to_shared(&s_w[1][0])};
    const int NG = Csub / CB;

    const bool wval = tid < CB * 36;
    uint32_t woff = 0;
    const float* wsrc = wt;
    {
        int c = tid / 36, rem = tid % 36, ij = rem / 4, q = rem % 4;
        woff = (uint32_t)(c * 144 + ij * 16 + 4 * q) * 4u;
        wsrc = wt + ((size_t)(cbase + c) * 9 + ij) * Co + (size_t)ocg * 16 + 4 * q;
    }
    const size_t wstep = (size_t)CB * 9 * Co;

    __syncthreads();

    auto stage_in = [&](int g, int buf) {
        uint32_t mb = mb0 + buf * 8;
        MBAR_EXPECT(mb, (uint32_t)(CB * TSZ * 4));
        int plane = b * Ci + cbase + g * CB;
        #pragma unroll
        for (int c = 0; c < CB; c++)
            TMA3D(sinA[buf] + c * CSZ * 4, &tmap, gc0, gr0, plane + c, mb);
    };
    auto stage_w = [&](int buf) {
        if (wval) cp_async16(swA[buf] + woff, wsrc);
        wsrc += wstep;
    };

    if (tid == 0) stage_in(0, 0);
    stage_w(0);
    CP_COMMIT();

    const int base_off = (4 * ty) * PITCH + 2 * tx + 3;

    for (int g = 0; g < NG; g++) {
        MBAR_WAIT(mb0 + (g & 1) * 8, (g >> 1) & 1);
        CP_WAIT0();
        __syncthreads();
        if (g + 1 < NG) {
            if (tid == 0) stage_in(g + 1, (g + 1) & 1);
            stage_w((g + 1) & 1);
            CP_COMMIT();
        }
        const int buf = g & 1;

        #pragma unroll
        for (int c = 0; c < CB; c++) {
            const float* sp = &s_in[buf][c * CSZ + base_off];
            float x[5][3];
            #pragma unroll
            for (int r = 0; r < 5; r++) {
                const float* rp = sp + r * PITCH;
                x[r][0] = rp[0]; x[r][1] = rp[1]; x[r][2] = rp[2];
            }
            const ulonglong2* wq = reinterpret_cast<const ulonglong2*>(&s_w[buf][c * 144]);
            #pragma unroll
            for (int i = 0; i < 3; i++)
            #pragma unroll
            for (int j = 0; j < 3; j++) {
                const int t = 3 * i + j;
                ulonglong2 w0 = wq[4*t], w1 = wq[4*t+1], w2 = wq[4*t+2], w3 = wq[4*t+3];
                float vA = x[i][j]     * kA[t];
                float vB = x[i + 2][j] * kB[t];
                u64 vvA, vvB;
                PACK2(vvA, vA, vA);
                PACK2(vvB, vB, vB);
                TAP16R(w0, w1, w2, w3, vvA, accA);
                TAP16R(w0, w1, w2, w3, vvB, accB);
            }
        }
    }

    if (S == 1) {
        #pragma unroll
        for (int p = 0; p < 8; p++) {
            int o = ocg * 16 + 2 * p;
            float a0, a1, b0v, b1v;
            UNPACK2(a0, a1, accA[p]);
            UNPACK2(b0v, b1v, accB[p]);
            float bias0 = bias[o], bias1 = bias[o + 1];
            float p00 = a0 + bias0, p01 = b0v + bias0;
            float p10 = a1 + bias1, p11 = b1v + bias1;
            p00 = p00 > 0.0f ? p00 : 0.0f;
            p01 = p01 > 0.0f ? p01 : 0.0f;
            p10 = p10 > 0.0f ? p10 : 0.0f;
            p11 = p11 > 0.0f ? p11 : 0.0f;
            float* o0p = &out[((size_t)(b * Co + o)     * Hout + oh0) * Wout + ow];
            float* o1p = &out[((size_t)(b * Co + o + 1) * Hout + oh0) * Wout + ow];
            o0p[0] = p00; o0p[Wout] = p01;
            o1p[0] = p10; o1p[Wout] = p11;
        }
    } else {
        float* pp = out + (size_t)sk * 2 * Co * Hout * Wout;
        #pragma unroll
        for (int p = 0; p < 8; p++) {
            int o = ocg * 16 + 2 * p;
            float a0, a1, b0v, b1v;
            UNPACK2(a0, a1, accA[p]);
            UNPACK2(b0v, b1v, accB[p]);
            float* o0p = &pp[((size_t)(b * Co + o)     * Hout + oh0) * Wout + ow];
            float* o1p = &pp[((size_t)(b * Co + o + 1) * Hout + oh0) * Wout + ow];
            o0p[0] = a0; o0p[Wout] = b0v;
            o1p[0] = a1; o1p[Wout] = b1v;
        }
    }
}

// ─── stride-2 small (Hout<32): 16x16 output tile, 1 px/thread, 16 outputs ───
__global__ void __launch_bounds__(256) conv_s2(
    const __grid_constant__ CUtensorMap tmap, const float* __restrict__ wt,
    const float* __restrict__ bias, const float* __restrict__ kern,
    float* __restrict__ out, int Ci, int Co, int H, int W, int tilesX,
    int Csub, int S)
{
    constexpr int CB = 2, PITCH = 40, TSZ = 33 * 40, CSZ = 1344;
    __shared__ __align__(128) float s_in[2][CB * CSZ];
    __shared__ __align__(16) float s_w[2][CB * 144];
    __shared__ __align__(8) unsigned long long s_mbar[2];

    const int tid = threadIdx.x;
    const int tx = tid % 16, ty = tid / 16;
    const int tX = blockIdx.x % tilesX, tY = blockIdx.x / tilesX;
    const int ocg = blockIdx.y;
    const int zz = blockIdx.z;
    const int b = zz & 1, sk = zz >> 1;
    const int cbase = sk * Csub;
    const int Hout = H / 2, Wout = W / 2;
    const int oh = tY * 16 + ty, ow = tX * 16 + tx;
    const size_t HW = (size_t)H * W;
    const int gr0 = tY * 32 - 1, gc0 = tX * 32 - 4;

    const uint32_t mb0 = (uint32_t)__cvta_generic_to_shared(&s_mbar[0]);
    if (tid == 0) { MBAR_INIT(mb0, 1); MBAR_INIT(mb0 + 8, 1); }

    float kreg[9];
    if (kern) {
        const float* kp = kern + (size_t)b * 9 * HW + (size_t)(oh * 2) * W + ow * 2;
        #pragma unroll
        for (int t = 0; t < 9; t++) kreg[t] = kp[(size_t)t * HW];
    } else {
        #pragma unroll
        for (int t = 0; t < 9; t++) kreg[t] = 1.0f;
    }

    u64 acc[8];
    #pragma unroll
    for (int p = 0; p < 8; p++) acc[p] = 0ull;

    const uint32_t sinA[2] = {(uint32_t)__cvta_generic_to_shared(&s_in[0][0]),
                              (uint32_t)__cvta_generic_to_shared(&s_in[1][0])};
    const uint32_t swA[2]  = {(uint32_t)__cvta_generic_to_shared(&s_w[0][0]),
                              (uint32_t)__cvta_generic_to_shared(&s_w[1][0])};
    const int NG = Csub / CB;

    const bool wval = tid < CB * 36;
    uint32_t woff = 0;
    const float* wsrc = wt;
    {
        int c = tid / 36, rem = tid % 36, ij = rem / 4, q = rem % 4;
        woff = (uint32_t)(c * 144 + ij * 16 + 4 * q) * 4u;
        wsrc = wt + ((size_t)(cbase + c) * 9 + ij) * Co + (size_t)ocg * 16 + 4 * q;
    }
    const size_t wstep = (size_t)CB * 9 * Co;

    __syncthreads();

    auto stage_in = [&](int g, int buf) {
        uint32_t mb = mb0 + buf * 8;
        MBAR_EXPECT(mb, (uint32_t)(CB * TSZ * 4));
        int plane = b * Ci + cbase + g * CB;
        #pragma unroll
        for (int c = 0; c < CB; c++)
            TMA3D(sinA[buf] + c * CSZ * 4, &tmap, gc0, gr0, plane + c, mb);
    };
    auto stage_w = [&](int buf) {
        if (wval) cp_async16(swA[buf] + woff, wsrc);
        wsrc += wstep;
    };

    if (tid == 0) stage_in(0, 0);
    stage_w(0);
    CP_COMMIT();

    const int base_off = (2 * ty) * PITCH + 2 * tx + 3;

    for (int g = 0; g < NG; g++) {
        MBAR_WAIT(mb0 + (g & 1) * 8, (g >> 1) & 1);
        CP_WAIT0();
        __syncthreads();
        if (g + 1 < NG) {
            if (tid == 0) stage_in(g + 1, (g + 1) & 1);
            stage_w((g + 1) & 1);
            CP_COMMIT();
        }
        const int buf = g & 1;

        #pragma unroll
        for (int c = 0; c < CB; c++) {
            const float* sp = &s_in[buf][c * CSZ + base_off];
            const ulonglong2* wq = reinterpret_cast<const ulonglong2*>(&s_w[buf][c * 144]);
            #pragma unroll
            for (int t = 0; t < 9; t++) {
                ulonglong2 w0 = wq[4*t], w1 = wq[4*t+1], w2 = wq[4*t+2], w3 = wq[4*t+3];
                float v = sp[(t / 3) * PITCH + (t % 3)] * kreg[t];
                u64 vv;
                PACK2(vv, v, v);
                TAP16R(w0, w1, w2, w3, vv, acc);
            }
        }
    }

    if (S == 1) {
        #pragma unroll
        for (int p = 0; p < 8; p++) {
            int o = ocg * 16 + 2 * p;
            float lo, hi;
            UNPACK2(lo, hi, acc[p]);
            float v0 = lo + bias[o], v1 = hi + bias[o + 1];
            v0 = v0 > 0.0f ? v0 : 0.0f;
            v1 = v1 > 0.0f ? v1 : 0.0f;
            out[((size_t)(b * Co + o)     * Hout + oh) * Wout + ow] = v0;
            out[((size_t)(b * Co + o + 1) * Hout + oh) * Wout + ow] = v1;
        }
    } else {
        float* pp = out + (size_t)sk * 2 * Co * Hout * Wout;
        #pragma unroll
        for (int p = 0; p < 8; p++) {
            int o = ocg * 16 + 2 * p;
            float lo, hi;
            UNPACK2(lo, hi, acc[p]);
            pp[((size_t)(b * Co + o)     * Hout + oh) * Wout + ow] = lo;
            pp[((size_t)(b * Co + o + 1) * Hout + oh) * Wout + ow] = hi;
        }
    }
}

__global__ void pac_gauss_kernel(const float* __restrict__ f, float* __restrict__ out,
                                 int C, int H, int W, float coeff2)
{
    const int b = blockIdx.z;
    const int idx = blockIdx.x * blockDim.x + threadIdx.x;
    if (idx >= H * W) return;
    const int h = idx / W, w = idx % W;

    float acc[9];
    #pragma unroll
    for (int t = 0; t < 9; t++) acc[t] = 0.0f;

    const float* fb = f + (size_t)b * C * H * W;
    for (int c = 0; c < C; c++) {
        const float* fc = fb + (size_t)c * H * W;
        float ctr = fc[idx];
        #pragma unroll
        for (int i = 0; i < 3; i++)
        #pragma unroll
        for (int j = 0; j < 3; j++) {
            int hh = h + i - 1, ww = w + j - 1;
            float nb = (hh >= 0 && hh < H && ww >= 0 && ww < W) ? fc[hh * W + ww] : 0.0f;
            float d = nb - ctr;
            acc[i * 3 + j] += d * d;
        }
    }

    float* ob = out + (size_t)b * 9 * H * W;
    #pragma unroll
    for (int t = 0; t < 9; t++)
        ob[(size_t)t * H * W + idx] = expf(-0.5f * coeff2 * acc[t]);
}

// ─── host side ───

typedef CUresult (CUDAAPI *PFN_encode)(
    CUtensorMap*, CUtensorMapDataType, cuuint32_t, void*,
    const cuuint64_t*, const cuuint64_t*, const cuuint32_t*, const cuuint32_t*,
    CUtensorMapInterleave, CUtensorMapSwizzle, CUtensorMapL2promotion,
    CUtensorMapFloatOOBfill);

static CUtensorMap h_maps[14];
static float* g_part_ptr;

static void make_map(PFN_encode enc, CUtensorMap* m, const void* base,
                     int W, int H, int planes, int boxw, int boxh)
{
    cuuint64_t dims[3] = {(cuuint64_t)W, (cuuint64_t)H, (cuuint64_t)planes};
    cuuint64_t strides[2] = {(cuuint64_t)W * 4, (cuuint64_t)W * H * 4};
    cuuint32_t box[3] = {(cuuint32_t)boxw, (cuuint32_t)boxh, 1};
    cuuint32_t es[3] = {1, 1, 1};
    enc(m, CU_TENSOR_MAP_DATA_TYPE_FLOAT32, 3, const_cast<void*>(base),
        dims, strides, box, es,
        CU_TENSOR_MAP_INTERLEAVE_NONE, CU_TENSOR_MAP_SWIZZLE_NONE,
        CU_TENSOR_MAP_L2_PROMOTION_L2_128B, CU_TENSOR_MAP_FLOAT_OOB_FILL_NONE);
}

static void conv_s1_l(const CUtensorMap& m, const float* wt, const float* b,
                      const float* kern, float* out, int Ci, int Co, int H, int W, int S)
{
    float* dst = (S > 1) ? g_part_ptr : out;
    if (W >= 32) {
        int tilesX = W / 32;
        dim3 grid(tilesX * (H / 16), Co / 16, 2 * S);
        if ((Ci / S) % 4 == 0)
            conv_s1<4><<<grid, 256>>>(m, wt, b, kern, dst, Ci, Co, H, W, tilesX, Ci / S, S);
        else
            conv_s1<1><<<grid, 256>>>(m, wt, b, kern, dst, Ci, Co, H, W, tilesX, Ci / S, S);
    } else {
        dim3 grid(1, Co / 16, 2 * S);
        conv_s1_16<<<grid, 256>>>(m, wt, b, kern, dst, Ci, Co, Ci / S, S);
    }
    if (S > 1) {
        int tot = 2 * Co * H * W;
        reduce_brelu<<<(tot + 255) / 256, 256>>>(g_part_ptr, b, out, Co, H * W, S, tot);
    }
}

static void conv_s2_l(const CUtensorMap& m, const float* wt, const float* b,
                      const float* kern, float* out, int Ci, int Co, int H, int W, int S)
{
    int Hout = H / 2, Wout = W / 2;
    float* dst = (S > 1) ? g_part_ptr : out;
    if (Hout >= 32) {
        int tilesX = Wout / 16;
        dim3 grid(tilesX * (Hout / 32), Co / 16, 2 * S);
        conv_s2v<<<grid, 256>>>(m, wt, b, kern, dst, Ci, Co, H, W, tilesX, Ci / S, S);
    } else {
        int tilesX = W / 32;
        dim3 grid(tilesX * (H / 32), Co / 16, 2 * S);
        conv_s2<<<grid, 256>>>(m, wt, b, kern, dst, Ci, Co, H, W, tilesX, Ci / S, S);
    }
    if (S > 1) {
        int tot = 2 * Co * Hout * Wout;
        reduce_brelu<<<(tot + 255) / 256, 256>>>(g_part_ptr, b, out, Co, Hout * Wout, S, tot);
    }
}

static void pac_layer(const float* f, float* out, int C, int H, int W, float coeff2)
{
    int hw = H * W;
    dim3 grid((hw + 255) / 256, 1, 2);
    pac_gauss_kernel<<<grid, 256>>>(f, out, C, H, W, coeff2);
}

extern "C" void kernel_launch(void* const* d_in, const int* in_sizes, int n_in,
                              void* d_out, int out_size)
{
    const float* x = (const float*)d_in[0];
    WPtrs wp;
    const float* B14[14];
    for (int i = 0; i < 14; i++) {
        wp.p[i] = (const float*)d_in[1 + 2 * i];
        B14[i]  = (const float*)d_in[2 + 2 * i];
    }

    float* bufA; float* bufB; float* wT;
    cudaGetSymbolAddress((void**)&bufA, g_bufA);
    cudaGetSymbolAddress((void**)&bufB, g_bufB);
    cudaGetSymbolAddress((void**)&wT,  g_wT);
    cudaGetSymbolAddress((void**)&g_part_ptr, g_part);

    static const size_t OFF[15] = {0,576,37440,74304,148032,295488,442944,737856,1327680,
                                   1917504,3097152,5456448,7815744,12534336,21971520};
    const float* wt[14];
    for (int l = 0; l < 14; l++) wt[l] = wT + OFF[l];

    float* out = (float*)d_out;
    float* h1 = out;
    float* h2 = h1 + 8388608;
    float* h3 = h2 + 4194304;
    float* h4 = h3 + 2097152;
    float* h5 = h4 + 1048576;
    float* k2 = h5 + 524288;
    float* k3 = k2 + 294912;
    float* k4 = k3 + 73728;
    float* k5 = k4 + 18432;

    PFN_encode enc = nullptr;
    cudaDriverEntryPointQueryResult qres;
#if CUDART_VERSION >= 12050
    cudaGetDriverEntryPointByVersion("cuTensorMapEncodeTiled", (void**)&enc, 12000,
                                     cudaEnableDefault, &qres);
#else
    cudaGetDriverEntryPoint("cuTensorMapEncodeTiled", (void**)&enc,
                            cudaEnableDefault, &qres);
#endif
    make_map(enc, &h_maps[0],  x,    256, 256, 2,    40, 18);
    make_map(enc, &h_maps[1],  bufA, 256, 256, 128,  40, 18);
    make_map(enc, &h_maps[2],  h1,   256, 256, 128,  40, 65);
    make_map(enc, &h_maps[3],  bufA, 128, 128, 128,  40, 18);
    make_map(enc, &h_maps[4],  bufB, 128, 128, 256,  40, 18);
    make_map(enc, &h_maps[5],  h2,   128, 128, 256,  40, 65);
    make_map(enc, &h_maps[6],  bufA, 64, 64, 256,    40, 18);
    make_map(enc, &h_maps[7],  bufB, 64, 64, 512,    40, 18);
    make_map(enc, &h_maps[8],  h3,   64, 64, 512,    40, 65);
    make_map(enc, &h_maps[9],  bufA, 32, 32, 512,    40, 18);
    make_map(enc, &h_maps[10], bufB, 32, 32, 1024,   40, 18);
    make_map(enc, &h_maps[11], h4,   32, 32, 1024,   40, 33);
    make_map(enc, &h_maps[12], bufA, 16, 16, 1024,   48, 18);
    make_map(enc, &h_maps[13], bufB, 16, 16, 2048,   48, 18);

    transpose_all_kernel<<<(21971520 + 255) / 256, 256>>>(wp, wT);

    const float KC2 = 1e-4f * 1e-4f;

    // Stage 1
    conv_s1_l(h_maps[0], wt[0], B14[0], nullptr, bufA, 1,  64, 256, 256, 1);
    conv_s1_l(h_maps[1], wt[1], B14[1], nullptr, h1,   64, 64, 256, 256, 1);
    conv_s2_l(h_maps[2], wt[2], B14[2], nullptr, bufA, 64, 64, 256, 256, 1);

    // Stage 2
    pac_layer(bufA, k2, 64, 128, 128, KC2);
    conv_s1_l(h_maps[3], wt[3], B14[3], k2, bufB, 64,  128, 128, 128, 1);
    conv_s1_l(h_maps[4], wt[4], B14[4], k2, h2,   128, 128, 128, 128, 1);
    conv_s2_l(h_maps[5], wt[5], B14[5], k2, bufA, 128, 128, 128, 128, 1);

    // Stage 3
    pac_layer(bufA, k3, 128, 64, 64, KC2);
    conv_s1_l(h_maps[6], wt[6], B14[6], k3, bufB, 128, 256, 64, 64, 1);
    conv_s1_l(h_maps[7], wt[7], B14[7], k3, h3,   256, 256, 64, 64, 1);
    conv_s2_l(h_maps[8], wt[8], B14[8], k3, bufA, 256, 256, 64, 64, 4);   // split-K

    // Stage 4
    pac_layer(bufA, k4, 256, 32, 32, 4.0f);
    conv_s1_l(h_maps[9],  wt[9],  B14[9],  k4, bufB, 256, 512, 32, 32, 4);  // split-K
    conv_s1_l(h_maps[10], wt[10], B14[10], k4, h4,   512, 512, 32, 32, 4);  // split-K
    conv_s2_l(h_maps[11], wt[11], B14[11], k4, bufA, 512, 512, 32, 32, 4);  // split-K

    // Stage 5
    pac_layer(bufA, k5, 512, 16, 16, KC2);
    conv_s1_l(h_maps[12], wt[12], B14[12], k5, bufB, 512,  1024, 16, 16, 4); // split-K
    conv_s1_l(h_maps[13], wt[13], B14[13], k5, h5,   1024, 1024, 16, 16, 4); // split-K
}

// round 13
// speedup vs baseline: 1.1111x; 1.0197x over previous
#include <cuda.h>
#include <cuda_runtime.h>
#include <cstdint>

typedef unsigned long long u64;

__device__ __align__(256) float g_bufA[8388608];
__device__ __align__(256) float g_bufB[4194304];
__device__ __align__(256) float g_wT [21971520];   // transposed weights [c][ij][o]
__device__ __align__(256) float g_part[4194304];   // split-K partial sums

__device__ __forceinline__ void cp_async16(uint32_t saddr, const float* gptr) {
    asm volatile("cp.async.cg.shared.global [%0], [%1], 16;" :: "r"(saddr), "l"(gptr));
}
#define CP_COMMIT() asm volatile("cp.async.commit_group;" ::: "memory")
#define CP_WAIT0()  asm volatile("cp.async.wait_group 0;" ::: "memory")
#define FFMA2(acc, w, v) asm("fma.rn.f32x2 %0, %1, %2, %0;" : "+l"(acc) : "l"(w), "l"(v))
#define PACK2(d, a, b)   asm("mov.b64 %0, {%1, %2};" : "=l"(d) : "f"(a), "f"(b))
#define UNPACK2(lo, hi, p) asm("mov.b64 {%0, %1}, %2;" : "=f"(lo), "=f"(hi) : "l"(p))

#define MBAR_INIT(mbar, cnt) \
    asm volatile("mbarrier.init.shared.b64 [%0], %1;" :: "r"(mbar), "r"(cnt) : "memory")
#define MBAR_EXPECT(mbar, bytes) \
    asm volatile("mbarrier.arrive.expect_tx.shared.b64 _, [%0], %1;" :: "r"(mbar), "r"(bytes) : "memory")
#define MBAR_WAIT(mbar, par) do { \
    asm volatile( \
        "{\n\t.reg .pred P1;\n\t" \
        "WAIT_LOOP_%=:\n\t" \
        "mbarrier.try_wait.parity.acquire.cta.shared::cta.b64 P1, [%0], %1, 0x989680;\n\t" \
        "@P1 bra.uni WAIT_DONE_%=;\n\t" \
        "bra.uni WAIT_LOOP_%=;\n\t" \
        "WAIT_DONE_%=:\n\t}" \
        :: "r"(mbar), "r"(par) : "memory"); \
} while(0)
#define TMA3D(dst, tmapp, cx, cy, cz, mbar) \
    asm volatile("cp.async.bulk.tensor.3d.shared::cta.global.tile.mbarrier::complete_tx::bytes " \
        "[%0], [%1, {%2, %3, %4}], [%5];" \
        :: "r"(dst), "l"(tmapp), "r"(cx), "r"(cy), "r"(cz), "r"(mbar) : "memory")

// ─── fused weight transpose ───
struct WPtrs { const float* p[14]; };

__global__ void transpose_all_kernel(WPtrs wp, float* __restrict__ wt)
{
    const int i = blockIdx.x * 256 + threadIdx.x;
    if (i >= 21971520) return;
    const int CiA[14] = {1,64,64, 64,128,128, 128,256,256, 256,512,512, 512,1024};
    const int CoA[14] = {64,64,64, 128,128,128, 256,256,256, 512,512,512, 1024,1024};
    const int OFF[15] = {0,576,37440,74304,148032,295488,442944,737856,1327680,
                         1917504,3097152,5456448,7815744,12534336,21971520};
    int l = 0;
    #pragma unroll
    for (int k = 1; k < 14; k++) if (i >= OFF[k]) l = k;
    int j = i - OFF[l];
    int Co = CoA[l], Ci = CiA[l];
    int o = j % Co;
    int cij = j / Co;
    int c = cij / 9, ij = cij % 9;
    wt[i] = wp.p[l][((size_t)o * Ci + c) * 9 + ij];
}

__global__ void reduce_brelu(const float* __restrict__ part, const float* __restrict__ bias,
                             float* __restrict__ out, int Co, int HW, int S, int tot)
{
    int idx = blockIdx.x * 256 + threadIdx.x;
    if (idx >= tot) return;
    int o = (idx / HW) % Co;
    float v = bias[o];
    for (int s = 0; s < S; s++) v += part[(size_t)s * tot + idx];
    out[idx] = v > 0.0f ? v : 0.0f;
}

#define TAP16R(w0, w1, w2, w3, vv, A)                                  \
    {                                                                  \
        FFMA2((A)[0], (w0).x, vv); FFMA2((A)[1], (w0).y, vv);          \
        FFMA2((A)[2], (w1).x, vv); FFMA2((A)[3], (w1).y, vv);          \
        FFMA2((A)[4], (w2).x, vv); FFMA2((A)[5], (w2).y, vv);          \
        FFMA2((A)[6], (w3).x, vv); FFMA2((A)[7], (w3).y, vv);          \
    }

// ─── stride-1 quad: 32x32 tile, 2x2 px/thread, 8 outs ───
// TMA tile 40x34 = 1360 floats; SMEM channel stride padded to 1376.
template<int CB>
__global__ void __launch_bounds__(256) conv_s1q(
    const __grid_constant__ CUtensorMap tmap, const float* __restrict__ wt,
    const float* __restrict__ bias, const float* __restrict__ kern,
    float* __restrict__ out, int Ci, int Co, int H, int W, int tilesX,
    int Csub, int S)
{
    constexpr int PITCH = 40, TSZ = 34 * 40, CSZ = 1376;
    __shared__ __align__(128) float s_in[2][CB * CSZ];
    __shared__ __align__(16) float s_w[2][CB * 72];
    __shared__ __align__(8) unsigned long long s_mbar[2];

    const int tid = threadIdx.x;
    const int lx = tid % 16, ty = tid / 16;
    const int tX = blockIdx.x % tilesX, tY = blockIdx.x / tilesX;
    const int ocg = blockIdx.y;
    const int zz = blockIdx.z;
    const int b = zz & 1, sk = zz >> 1;
    const int cbase = sk * Csub;
    const int oh0 = tY * 32 + 2 * ty, ow0 = tX * 32 + 2 * lx;
    const size_t HW = (size_t)H * W;
    const int gr0 = tY * 32 - 1, gc0 = tX * 32 - 4;

    const uint32_t mb0 = (uint32_t)__cvta_generic_to_shared(&s_mbar[0]);
    if (tid == 0) { MBAR_INIT(mb0, 1); MBAR_INIT(mb0 + 8, 1); }

    // PAC kernel values for 4 pixels: [2r+c][t]
    float kk[4][9];
    if (kern) {
        const float* kp = kern + (size_t)b * 9 * HW + (size_t)oh0 * W + ow0;
        #pragma unroll
        for (int t = 0; t < 9; t++) {
            float2 r0 = *(const float2*)(kp + (size_t)t * HW);
            float2 r1 = *(const float2*)(kp + (size_t)t * HW + W);
            kk[0][t] = r0.x; kk[1][t] = r0.y;
            kk[2][t] = r1.x; kk[3][t] = r1.y;
        }
    } else {
        #pragma unroll
        for (int p = 0; p < 4; p++)
        #pragma unroll
        for (int t = 0; t < 9; t++) kk[p][t] = 1.0f;
    }

    u64 acc[16];   // acc[p*4+q]: pixel p, outputs (2q,2q+1)
    #pragma unroll
    for (int p = 0; p < 16; p++) acc[p] = 0ull;

    const uint32_t sinA[2] = {(uint32_t)__cvta_generic_to_shared(&s_in[0][0]),
                              (uint32_t)__cvta_generic_to_shared(&s_in[1][0])};
    const uint32_t swA[2]  = {(uint32_t)__cvta_generic_to_shared(&s_w[0][0]),
                              (uint32_t)__cvta_generic_to_shared(&s_w[1][0])};
    const int NG = Csub / CB;

    const bool wval = tid < CB * 18;
    uint32_t woff = 0;
    const float* wsrc = wt;
    {
        int c = tid / 18, rem = tid % 18, ij = rem / 2, q = rem % 2;
        woff = (uint32_t)(c * 72 + ij * 8 + 4 * q) * 4u;
        wsrc = wt + ((size_t)(cbase + c) * 9 + ij) * Co + (size_t)ocg * 8 + 4 * q;
    }
    const size_t wstep = (size_t)CB * 9 * Co;

    __syncthreads();

    auto stage_in = [&](int g, int buf) {
        uint32_t mb = mb0 + buf * 8;
        MBAR_EXPECT(mb, (uint32_t)(CB * TSZ * 4));
        int plane = b * Ci + cbase + g * CB;
        #pragma unroll
        for (int c = 0; c < CB; c++)
            TMA3D(sinA[buf] + c * CSZ * 4, &tmap, gc0, gr0, plane + c, mb);
    };
    auto stage_w = [&](int buf) {
        if (wval) cp_async16(swA[buf] + woff, wsrc);
        wsrc += wstep;
    };

    if (tid == 0) stage_in(0, 0);
    stage_w(0);
    CP_COMMIT();

    const int base_off = (2 * ty) * PITCH + 2 * lx + 3;

    for (int g = 0; g < NG; g++) {
        MBAR_WAIT(mb0 + (g & 1) * 8, (g >> 1) & 1);
        CP_WAIT0();
        __syncthreads();
        if (g + 1 < NG) {
            if (tid == 0) stage_in(g + 1, (g + 1) & 1);
            stage_w((g + 1) & 1);
            CP_COMMIT();
        }
        const int buf = g & 1;

        #pragma unroll
        for (int c = 0; c < CB; c++) {
            const float* sp = &s_in[buf][c * CSZ + base_off];
            float x[4][4];
            #pragma unroll
            for (int r = 0; r < 4; r++) {
                const float* rp = sp + r * PITCH;
                x[r][0] = rp[0];
                float2 xm = *(const float2*)(rp + 1);
                x[r][1] = xm.x; x[r][2] = xm.y;
                x[r][3] = rp[3];
            }
            const ulonglong2* wq = reinterpret_cast<const ulonglong2*>(&s_w[buf][c * 72]);
            #pragma unroll
            for (int i = 0; i < 3; i++)
            #pragma unroll
            for (int j = 0; j < 3; j++) {
                const int t = 3 * i + j;
                ulonglong2 wa = wq[2 * t], wb = wq[2 * t + 1];
                float v00 = x[i][j]     * kk[0][t];
                float v01 = x[i][j + 1] * kk[1][t];
                float v10 = x[i + 1][j]     * kk[2][t];
                float v11 = x[i + 1][j + 1] * kk[3][t];
                u64 p00, p01, p10, p11;
                PACK2(p00, v00, v00);
                PACK2(p01, v01, v01);
                PACK2(p10, v10, v10);
                PACK2(p11, v11, v11);
                FFMA2(acc[0],  wa.x, p00); FFMA2(acc[1],  wa.y, p00);
                FFMA2(acc[2],  wb.x, p00); FFMA2(acc[3],  wb.y, p00);
                FFMA2(acc[4],  wa.x, p01); FFMA2(acc[5],  wa.y, p01);
                FFMA2(acc[6],  wb.x, p01); FFMA2(acc[7],  wb.y, p01);
                FFMA2(acc[8],  wa.x, p10); FFMA2(acc[9],  wa.y, p10);
                FFMA2(acc[10], wb.x, p10); FFMA2(acc[11], wb.y, p10);
                FFMA2(acc[12], wa.x, p11); FFMA2(acc[13], wa.y, p11);
                FFMA2(acc[14], wb.x, p11); FFMA2(acc[15], wb.y, p11);
            }
        }
    }

    if (S == 1) {
        #pragma unroll
        for (int q = 0; q < 4; q++) {
            int o0 = ocg * 8 + 2 * q;
            float a00, a01, a10, a11, a20, a21, a30, a31;
            UNPACK2(a00, a01, acc[q]);        // px(r0,c0): o0, o0+1
            UNPACK2(a10, a11, acc[4 + q]);    // px(r0,c1)
            UNPACK2(a20, a21, acc[8 + q]);    // px(r1,c0)
            UNPACK2(a30, a31, acc[12 + q]);   // px(r1,c1)
            float b0 = bias[o0], b1 = bias[o0 + 1];
            float r00 = a00 + b0, r01 = a10 + b0, r02 = a20 + b0, r03 = a30 + b0;
            float r10 = a01 + b1, r11 = a11 + b1, r12 = a21 + b1, r13 = a31 + b1;
            r00 = r00 > 0.0f ? r00 : 0.0f; r01 = r01 > 0.0f ? r01 : 0.0f;
            r02 = r02 > 0.0f ? r02 : 0.0f; r03 = r03 > 0.0f ? r03 : 0.0f;
            r10 = r10 > 0.0f ? r10 : 0.0f; r11 = r11 > 0.0f ? r11 : 0.0f;
            r12 = r12 > 0.0f ? r12 : 0.0f; r13 = r13 > 0.0f ? r13 : 0.0f;
            float* p0 = &out[((size_t)(b * Co + o0)     * H + oh0) * W + ow0];
            float* p1 = &out[((size_t)(b * Co + o0 + 1) * H + oh0) * W + ow0];
            *(float2*)p0       = make_float2(r00, r01);
            *(float2*)(p0 + W) = make_float2(r02, r03);
            *(float2*)p1       = make_float2(r10, r11);
            *(float2*)(p1 + W) = make_float2(r12, r13);
        }
    } else {
        float* pp = out + (size_t)sk * 2 * Co * HW;
        #pragma unroll
        for (int q = 0; q < 4; q++) {
            int o0 = ocg * 8 + 2 * q;
            float a00, a01, a10, a11, a20, a21, a30, a31;
            UNPACK2(a00, a01, acc[q]);
            UNPACK2(a10, a11, acc[4 + q]);
            UNPACK2(a20, a21, acc[8 + q]);
            UNPACK2(a30, a31, acc[12 + q]);
            float* p0 = &pp[((size_t)(b * Co + o0)     * H + oh0) * W + ow0];
            float* p1 = &pp[((size_t)(b * Co + o0 + 1) * H + oh0) * W + ow0];
            *(float2*)p0       = make_float2(a00, a10);
            *(float2*)(p0 + W) = make_float2(a20, a30);
            *(float2*)p1       = make_float2(a01, a11);
            *(float2*)(p1 + W) = make_float2(a21, a31);
        }
    }
}

// ─── stride-1, 16x16 images: 1 px/thread, 16 outs ───
__global__ void __launch_bounds__(256) conv_s1_16(
    const __grid_constant__ CUtensorMap tmap, const float* __restrict__ wt,
    const float* __restrict__ bias, const float* __restrict__ kern,
    float* __restrict__ out, int Ci, int Co, int Csub, int S)
{
    constexpr int CB = 4, PITCH = 48, TSZ = 18 * 48, CSZ = 864;
    __shared__ __align__(128) float s_in[2][CB * CSZ];
    __shared__ __align__(16) float s_w[2][CB * 144];
    __shared__ __align__(8) unsigned long long s_mbar[2];

    const int tid = threadIdx.x;
    const int tx = tid % 16, ty = tid / 16;
    const int ocg = blockIdx.y;
    const int zz = blockIdx.z;
    const int b = zz & 1, sk = zz >> 1;
    const int cbase = sk * Csub;
    const size_t HW = 256;

    const uint32_t mb0 = (uint32_t)__cvta_generic_to_shared(&s_mbar[0]);
    if (tid == 0) { MBAR_INIT(mb0, 1); MBAR_INIT(mb0 + 8, 1); }

    float kreg[9];
    {
        const float* kp = kern + (size_t)b * 9 * HW + (size_t)ty * 16 + tx;
        #pragma unroll
        for (int t = 0; t < 9; t++) kreg[t] = kp[(size_t)t * HW];
    }

    u64 acc[8];
    #pragma unroll
    for (int p = 0; p < 8; p++) acc[p] = 0ull;

    const uint32_t sinA[2] = {(uint32_t)__cvta_generic_to_shared(&s_in[0][0]),
                              (uint32_t)__cvta_generic_to_shared(&s_in[1][0])};
    const uint32_t swA[2]  = {(uint32_t)__cvta_generic_to_shared(&s_w[0][0]),
                              (uint32_t)__cvta_generic_to_shared(&s_w[1][0])};
    const int NG = Csub / CB;

    const bool wval = tid < CB * 36;
    uint32_t woff = 0;
    const float* wsrc = wt;
    {
        int c = tid / 36, rem = tid % 36, ij = rem / 4, q = rem % 4;
        woff = (uint32_t)(c * 144 + ij * 16 + 4 * q) * 4u;
        wsrc = wt + ((size_t)(cbase + c) * 9 + ij) * Co + (size_t)ocg * 16 + 4 * q;
    }
    const size_t wstep = (size_t)CB * 9 * Co;

    __syncthreads();

    auto stage_in = [&](int g, int buf) {
        uint32_t mb = mb0 + buf * 8;
        MBAR_EXPECT(mb, (uint32_t)(CB * TSZ * 4));
        int plane = b * Ci + cbase + g * CB;
        #pragma unroll
        for (int c = 0; c < CB; c++)
            TMA3D(sinA[buf] + c * CSZ * 4, &tmap, -4, -1, plane + c, mb);
    };
    auto stage_w = [&](int buf) {
        if (wval) cp_async16(swA[buf] + woff, wsrc);
        wsrc += wstep;
    };

    if (tid == 0) stage_in(0, 0);
    stage_w(0);
    CP_COMMIT();

    const int base_off = ty * PITCH + tx + 3;

    for (int g = 0; g < NG; g++) {
        MBAR_WAIT(mb0 + (g & 1) * 8, (g >> 1) & 1);
        CP_WAIT0();
        __syncthreads();
        if (g + 1 < NG) {
            if (tid == 0) stage_in(g + 1, (g + 1) & 1);
            stage_w((g + 1) & 1);
            CP_COMMIT();
        }
        const int buf = g & 1;

        #pragma unroll
        for (int c = 0; c < CB; c++) {
            const float* sp = &s_in[buf][c * CSZ + base_off];
            const ulonglong2* wq = reinterpret_cast<const ulonglong2*>(&s_w[buf][c * 144]);
            #pragma unroll
            for (int t = 0; t < 9; t++) {
                ulonglong2 w0 = wq[4*t], w1 = wq[4*t+1], w2 = wq[4*t+2], w3 = wq[4*t+3];
                float v = sp[(t / 3) * PITCH + (t % 3)] * kreg[t];
                u64 vv;
                PACK2(vv, v, v);
                TAP16R(w0, w1, w2, w3, vv, acc);
            }
        }
    }

    if (S == 1) {
        #pragma unroll
        for (int p = 0; p < 8; p++) {
            int o = ocg * 16 + 2 * p;
            float lo, hi;
            UNPACK2(lo, hi, acc[p]);
            float v0 = lo + bias[o], v1 = hi + bias[o + 1];
            v0 = v0 > 0.0f ? v0 : 0.0f;
            v1 = v1 > 0.0f ? v1 : 0.0f;
            out[((size_t)(b * Co + o)     * 16 + ty) * 16 + tx] = v0;
            out[((size_t)(b * Co + o + 1) * 16 + ty) * 16 + tx] = v1;
        }
    } else {
        float* pp = out + (size_t)sk * 2 * Co * HW;
        #pragma unroll
        for (int p = 0; p < 8; p++) {
            int o = ocg * 16 + 2 * p;
            float lo, hi;
            UNPACK2(lo, hi, acc[p]);
            pp[((size_t)(b * Co + o)     * 16 + ty) * 16 + tx] = lo;
            pp[((size_t)(b * Co + o + 1) * 16 + ty) * 16 + tx] = hi;
        }
    }
}

// ─── stride-2 vertical-pair: 16x32 out tile, 2 px/thread, 16 outs ───
__global__ void __launch_bounds__(256) conv_s2v(
    const __grid_constant__ CUtensorMap tmap, const float* __restrict__ wt,
    const float* __restrict__ bias, const float* __restrict__ kern,
    float* __restrict__ out, int Ci, int Co, int H, int W, int tilesX,
    int Csub, int S)
{
    constexpr int CB = 2, PITCH = 40, TSZ = 65 * 40, CSZ = 2624;
    __shared__ __align__(128) float s_in[2][CB * CSZ];
    __shared__ __align__(16) float s_w[2][CB * 144];
    __shared__ __align__(8) unsigned long long s_mbar[2];

    const int tid = threadIdx.x;
    const int tx = tid % 16, ty = tid / 16;
    const int tX = blockIdx.x % tilesX, tY = blockIdx.x / tilesX;
    const int ocg = blockIdx.y;
    const int zz = blockIdx.z;
    const int b = zz & 1, sk = zz >> 1;
    const int cbase = sk * Csub;
    const int Hout = H / 2, Wout = W / 2;
    const int oh0 = tY * 32 + 2 * ty;
    const int ow = tX * 16 + tx;
    const size_t HW = (size_t)H * W;
    const int gr0 = tY * 64 - 1, gc0 = tX * 32 - 4;

    const uint32_t mb0 = (uint32_t)__cvta_generic_to_shared(&s_mbar[0]);
    if (tid == 0) { MBAR_INIT(mb0, 1); MBAR_INIT(mb0 + 8, 1); }

    float kA[9], kB[9];
    if (kern) {
        const float* kp = kern + (size_t)b * 9 * HW + (size_t)(oh0 * 2) * W + ow * 2;
        #pragma unroll
        for (int t = 0; t < 9; t++) {
            kA[t] = kp[(size_t)t * HW];
            kB[t] = kp[(size_t)t * HW + 2 * W];
        }
    } else {
        #pragma unroll
        for (int t = 0; t < 9; t++) { kA[t] = 1.0f; kB[t] = 1.0f; }
    }

    u64 accA[8], accB[8];
    #pragma unroll
    for (int p = 0; p < 8; p++) { accA[p] = 0ull; accB[p] = 0ull; }

    const uint32_t sinA[2] = {(uint32_t)__cvta_generic_to_shared(&s_in[0][0]),
                              (uint32_t)__cvta_generic_to_shared(&s_in[1][0])};
    const uint32_t swA[2]  = {(uint32_t)__cvta_generic_to_shared(&s_w[0][0]),
                              (uint32_t)__cvta_generic_to_shared(&s_w[1][0])};
    const int NG = Csub / CB;

    const bool wval = tid < CB * 36;
    uint32_t woff = 0;
    const float* wsrc = wt;
    {
        int c = tid / 36, rem = tid % 36, ij = rem / 4, q = rem % 4;
        woff = (uint32_t)(c * 144 + ij * 16 + 4 * q) * 4u;
        wsrc = wt + ((size_t)(cbase + c) * 9 + ij) * Co + (size_t)ocg * 16 + 4 * q;
    }
    const size_t wstep = (size_t)CB * 9 * Co;

    __syncthreads();

    auto stage_in = [&](int g, int buf) {
        uint32_t mb = mb0 + buf * 8;
        MBAR_EXPECT(mb, (uint32_t)(CB * TSZ * 4));
        int plane = b * Ci + cbase + g * CB;
        #pragma unroll
        for (int c = 0; c < CB; c++)
            TMA3D(sinA[buf] + c * CSZ * 4, &tmap, gc0, gr0, plane + c, mb);
    };
    auto stage_w = [&](int buf) {
        if (wval) cp_async16(swA[buf] + woff, wsrc);
        wsrc += wstep;
    };

    if (tid == 0) stage_in(0, 0);
    stage_w(0);
    CP_COMMIT();

    const int base_off = (4 * ty) * PITCH + 2 * tx + 3;

    for (int g = 0; g < NG; g++) {
        MBAR_WAIT(mb0 + (g & 1) * 8, (g >> 1) & 1);
        CP_WAIT0();
        __syncthreads();
        if (g + 1 < NG) {
            if (tid == 0) stage_in(g + 1, (g + 1) & 1);
            stage_w((g + 1) & 1);
            CP_COMMIT();
        }
        const int buf = g & 1;

        #pragma unroll
        for (int c = 0; c < CB; c++) {
            const float* sp = &s_in[buf][c * CSZ + base_off];
            float x[5][3];
            #pragma unroll
            for (int r = 0; r < 5; r++) {
                const float* rp = sp + r * PITCH;
                x[r][0] = rp[0]; x[r][1] = rp[1]; x[r][2] = rp[2];
            }
            const ulonglong2* wq = reinterpret_cast<const ulonglong2*>(&s_w[buf][c * 144]);
            #pragma unroll
            for (int i = 0; i < 3; i++)
            #pragma unroll
            for (int j = 0; j < 3; j++) {
                const int t = 3 * i + j;
                ulonglong2 w0 = wq[4*t], w1 = wq[4*t+1], w2 = wq[4*t+2], w3 = wq[4*t+3];
                float vA = x[i][j]     * kA[t];
                float vB = x[i + 2][j] * kB[t];
                u64 vvA, vvB;
                PACK2(vvA, vA, vA);
                PACK2(vvB, vB, vB);
                TAP16R(w0, w1, w2, w3, vvA, accA);
                TAP16R(w0, w1, w2, w3, vvB, accB);
            }
        }
    }

    if (S == 1) {
        #pragma unroll
        for (int p = 0; p < 8; p++) {
            int o = ocg * 16 + 2 * p;
            float a0, a1, b0v, b1v;
            UNPACK2(a0, a1, accA[p]);
            UNPACK2(b0v, b1v, accB[p]);
            float bias0 = bias[o], bias1 = bias[o + 1];
            float p00 = a0 + bias0, p01 = b0v + bias0;
            float p10 = a1 + bias1, p11 = b1v + bias1;
            p00 = p00 > 0.0f ? p00 : 0.0f;
            p01 = p01 > 0.0f ? p01 : 0.0f;
            p10 = p10 > 0.0f ? p10 : 0.0f;
            p11 = p11 > 0.0f ? p11 : 0.0f;
            float* o0p = &out[((size_t)(b * Co + o)     * Hout + oh0) * Wout + ow];
            float* o1p = &out[((size_t)(b * Co + o + 1) * Hout + oh0) * Wout + ow];
            o0p[0] = p00; o0p[Wout] = p01;
            o1p[0] = p10; o1p[Wout] = p11;
        }
    } else {
        float* pp = out + (size_t)sk * 2 * Co * Hout * Wout;
        #pragma unroll
        for (int p = 0; p < 8; p++) {
            int o = ocg * 16 + 2 * p;
            float a0, a1, b0v, b1v;
            UNPACK2(a0, a1, accA[p]);
            UNPACK2(b0v, b1v, accB[p]);
            float* o0p = &pp[((size_t)(b * Co + o)     * Hout + oh0) * Wout + ow];
            float* o1p = &pp[((size_t)(b * Co + o + 1) * Hout + oh0) * Wout + ow];
            o0p[0] = a0; o0p[Wout] = b0v;
            o1p[0] = a1; o1p[Wout] = b1v;
        }
    }
}

// ─── stride-2 small (Hout<32): 16x16 out tile, 1 px/thread, 16 outs ───
__global__ void __launch_bounds__(256) conv_s2(
    const __grid_constant__ CUtensorMap tmap, const float* __restrict__ wt,
    const float* __restrict__ bias, const float* __restrict__ kern,
    float* __restrict__ out, int Ci, int Co, int H, int W, int tilesX,
    int Csub, int S)
{
    constexpr int CB = 2, PITCH = 40, TSZ = 33 * 40, CSZ = 1344;
    __shared__ __align__(128) float s_in[2][CB * CSZ];
    __shared__ __align__(16) float s_w[2][CB * 144];
    __shared__ __align__(8) unsigned long long s_mbar[2];

    const int tid = threadIdx.x;
    const int tx = tid % 16, ty = tid / 16;
    const int tX = blockIdx.x % tilesX, tY = blockIdx.x / tilesX;
    const int ocg = blockIdx.y;
    const int zz = blockIdx.z;
    const int b = zz & 1, sk = zz >> 1;
    const int cbase = sk * Csub;
    const int Hout = H / 2, Wout = W / 2;
    const int oh = tY * 16 + ty, ow = tX * 16 + tx;
    const size_t HW = (size_t)H * W;
    const int gr0 = tY * 32 - 1, gc0 = tX * 32 - 4;

    const uint32_t mb0 = (uint32_t)__cvta_generic_to_shared(&s_mbar[0]);
    if (tid == 0) { MBAR_INIT(mb0, 1); MBAR_INIT(mb0 + 8, 1); }

    float kreg[9];
    if (kern) {
        const float* kp = kern + (size_t)b * 9 * HW + (size_t)(oh * 2) * W + ow * 2;
        #pragma unroll
        for (int t = 0; t < 9; t++) kreg[t] = kp[(size_t)t * HW];
    } else {
        #pragma unroll
        for (int t = 0; t < 9; t++) kreg[t] = 1.0f;
    }

    u64 acc[8];
    #pragma unroll
    for (int p = 0; p < 8; p++) acc[p] = 0ull;

    const uint32_t sinA[2] = {(uint32_t)__cvta_generic_to_shared(&s_in[0][0]),
                              (uint32_t)__cvta_generic_to_shared(&s_in[1][0])};
    const uint32_t swA[2]  = {(uint32_t)__cvta_generic_to_shared(&s_w[0][0]),
                              (uint32_t)__cvta_generic_to_shared(&s_w[1][0])};
    const int NG = Csub / CB;

    const bool wval = tid < CB * 36;
    uint32_t woff = 0;
    const float* wsrc = wt;
    {
        int c = tid / 36, rem = tid % 36, ij = rem / 4, q = rem % 4;
        woff = (uint32_t)(c * 144 + ij * 16 + 4 * q) * 4u;
        wsrc = wt + ((size_t)(cbase + c) * 9 + ij) * Co + (size_t)ocg * 16 + 4 * q;
    }
    const size_t wstep = (size_t)CB * 9 * Co;

    __syncthreads();

    auto stage_in = [&](int g, int buf) {
        uint32_t mb = mb0 + buf * 8;
        MBAR_EXPECT(mb, (uint32_t)(CB * TSZ * 4));
        int plane = b * Ci + cbase + g * CB;
        #pragma unroll
        for (int c = 0; c < CB; c++)
            TMA3D(sinA[buf] + c * CSZ * 4, &tmap, gc0, gr0, plane + c, mb);
    };
    auto stage_w = [&](int buf) {
        if (wval) cp_async16(swA[buf] + woff, wsrc);
        wsrc += wstep;
    };

    if (tid == 0) stage_in(0, 0);
    stage_w(0);
    CP_COMMIT();

    const int base_off = (2 * ty) * PITCH + 2 * tx + 3;

    for (int g = 0; g < NG; g++) {
        MBAR_WAIT(mb0 + (g & 1) * 8, (g >> 1) & 1);
        CP_WAIT0();
        __syncthreads();
        if (g + 1 < NG) {
            if (tid == 0) stage_in(g + 1, (g + 1) & 1);
            stage_w((g + 1) & 1);
            CP_COMMIT();
        }
        const int buf = g & 1;

        #pragma unroll
        for (int c = 0; c < CB; c++) {
            const float* sp = &s_in[buf][c * CSZ + base_off];
            const ulonglong2* wq = reinterpret_cast<const ulonglong2*>(&s_w[buf][c * 144]);
            #pragma unroll
            for (int t = 0; t < 9; t++) {
                ulonglong2 w0 = wq[4*t], w1 = wq[4*t+1], w2 = wq[4*t+2], w3 = wq[4*t+3];
                float v = sp[(t / 3) * PITCH + (t % 3)] * kreg[t];
                u64 vv;
                PACK2(vv, v, v);
                TAP16R(w0, w1, w2, w3, vv, acc);
            }
        }
    }

    if (S == 1) {
        #pragma unroll
        for (int p = 0; p < 8; p++) {
            int o = ocg * 16 + 2 * p;
            float lo, hi;
            UNPACK2(lo, hi, acc[p]);
            float v0 = lo + bias[o], v1 = hi + bias[o + 1];
            v0 = v0 > 0.0f ? v0 : 0.0f;
            v1 = v1 > 0.0f ? v1 : 0.0f;
            out[((size_t)(b * Co + o)     * Hout + oh) * Wout + ow] = v0;
            out[((size_t)(b * Co + o + 1) * Hout + oh) * Wout + ow] = v1;
        }
    } else {
        float* pp = out + (size_t)sk * 2 * Co * Hout * Wout;
        #pragma unroll
        for (int p = 0; p < 8; p++) {
            int o = ocg * 16 + 2 * p;
            float lo, hi;
            UNPACK2(lo, hi, acc[p]);
            pp[((size_t)(b * Co + o)     * Hout + oh) * Wout + ow] = lo;
            pp[((size_t)(b * Co + o + 1) * Hout + oh) * Wout + ow] = hi;
        }
    }
}

__global__ void pac_gauss_kernel(const float* __restrict__ f, float* __restrict__ out,
                                 int C, int H, int W, float coeff2)
{
    const int b = blockIdx.z;
    const int idx = blockIdx.x * blockDim.x + threadIdx.x;
    if (idx >= H * W) return;
    const int h = idx / W, w = idx % W;

    float acc[9];
    #pragma unroll
    for (int t = 0; t < 9; t++) acc[t] = 0.0f;

    const float* fb = f + (size_t)b * C * H * W;
    for (int c = 0; c < C; c++) {
        const float* fc = fb + (size_t)c * H * W;
        float ctr = fc[idx];
        #pragma unroll
        for (int i = 0; i < 3; i++)
        #pragma unroll
        for (int j = 0; j < 3; j++) {
            int hh = h + i - 1, ww = w + j - 1;
            float nb = (hh >= 0 && hh < H && ww >= 0 && ww < W) ? fc[hh * W + ww] : 0.0f;
            float d = nb - ctr;
            acc[i * 3 + j] += d * d;
        }
    }

    float* ob = out + (size_t)b * 9 * H * W;
    #pragma unroll
    for (int t = 0; t < 9; t++)
        ob[(size_t)t * H * W + idx] = expf(-0.5f * coeff2 * acc[t]);
}

// ─── host side ───

typedef CUresult (CUDAAPI *PFN_encode)(
    CUtensorMap*, CUtensorMapDataType, cuuint32_t, void*,
    const cuuint64_t*, const cuuint64_t*, const cuuint32_t*, const cuuint32_t*,
    CUtensorMapInterleave, CUtensorMapSwizzle, CUtensorMapL2promotion,
    CUtensorMapFloatOOBfill);

static CUtensorMap h_maps[14];
static float* g_part_ptr;

static void make_map(PFN_encode enc, CUtensorMap* m, const void* base,
                     int W, int H, int planes, int boxw, int boxh)
{
    cuuint64_t dims[3] = {(cuuint64_t)W, (cuuint64_t)H, (cuuint64_t)planes};
    cuuint64_t strides[2] = {(cuuint64_t)W * 4, (cuuint64_t)W * H * 4};
    cuuint32_t box[3] = {(cuuint32_t)boxw, (cuuint32_t)boxh, 1};
    cuuint32_t es[3] = {1, 1, 1};
    enc(m, CU_TENSOR_MAP_DATA_TYPE_FLOAT32, 3, const_cast<void*>(base),
        dims, strides, box, es,
        CU_TENSOR_MAP_INTERLEAVE_NONE, CU_TENSOR_MAP_SWIZZLE_NONE,
        CU_TENSOR_MAP_L2_PROMOTION_L2_128B, CU_TENSOR_MAP_FLOAT_OOB_FILL_NONE);
}

static void conv_s1_l(const CUtensorMap& m, const float* wt, const float* b,
                      const float* kern, float* out, int Ci, int Co, int H, int W, int S)
{
    float* dst = (S > 1) ? g_part_ptr : out;
    if (W >= 32) {
        int tilesX = W / 32;
        dim3 grid(tilesX * (H / 32), Co / 8, 2 * S);
        if ((Ci / S) % 4 == 0)
            conv_s1q<4><<<grid, 256>>>(m, wt, b, kern, dst, Ci, Co, H, W, tilesX, Ci / S, S);
        else
            conv_s1q<1><<<grid, 256>>>(m, wt, b, kern, dst, Ci, Co, H, W, tilesX, Ci / S, S);
    } else {
        dim3 grid(1, Co / 16, 2 * S);
        conv_s1_16<<<grid, 256>>>(m, wt, b, kern, dst, Ci, Co, Ci / S, S);
    }
    if (S > 1) {
        int tot = 2 * Co * H * W;
        reduce_brelu<<<(tot + 255) / 256, 256>>>(g_part_ptr, b, out, Co, H * W, S, tot);
    }
}

static void conv_s2_l(const CUtensorMap& m, const float* wt, const float* b,
                      const float* kern, float* out, int Ci, int Co, int H, int W, int S)
{
    int Hout = H / 2, Wout = W / 2;
    float* dst = (S > 1) ? g_part_ptr : out;
    if (Hout >= 32) {
        int tilesX = Wout / 16;
        dim3 grid(tilesX * (Hout / 32), Co / 16, 2 * S);
        conv_s2v<<<grid, 256>>>(m, wt, b, kern, dst, Ci, Co, H, W, tilesX, Ci / S, S);
    } else {
        int tilesX = W / 32;
        dim3 grid(tilesX * (H / 32), Co / 16, 2 * S);
        conv_s2<<<grid, 256>>>(m, wt, b, kern, dst, Ci, Co, H, W, tilesX, Ci / S, S);
    }
    if (S > 1) {
        int tot = 2 * Co * Hout * Wout;
        reduce_brelu<<<(tot + 255) / 256, 256>>>(g_part_ptr, b, out, Co, Hout * Wout, S, tot);
    }
}

static void pac_layer(const float* f, float* out, int C, int H, int W, float coeff2)
{
    int hw = H * W;
    dim3 grid((hw + 255) / 256, 1, 2);
    pac_gauss_kernel<<<grid, 256>>>(f, out, C, H, W, coeff2);
}

extern "C" void kernel_launch(void* const* d_in, const int* in_sizes, int n_in,
                              void* d_out, int out_size)
{
    const float* x = (const float*)d_in[0];
    WPtrs wp;
    const float* B14[14];
    for (int i = 0; i < 14; i++) {
        wp.p[i] = (const float*)d_in[1 + 2 * i];
        B14[i]  = (const float*)d_in[2 + 2 * i];
    }

    float* bufA; float* bufB; float* wT;
    cudaGetSymbolAddress((void**)&bufA, g_bufA);
    cudaGetSymbolAddress((void**)&bufB, g_bufB);
    cudaGetSymbolAddress((void**)&wT,  g_wT);
    cudaGetSymbolAddress((void**)&g_part_ptr, g_part);

    static const size_t OFF[15] = {0,576,37440,74304,148032,295488,442944,737856,1327680,
                                   1917504,3097152,5456448,7815744,12534336,21971520};
    const float* wt[14];
    for (int l = 0; l < 14; l++) wt[l] = wT + OFF[l];

    float* out = (float*)d_out;
    float* h1 = out;
    float* h2 = h1 + 8388608;
    float* h3 = h2 + 4194304;
    float* h4 = h3 + 2097152;
    float* h5 = h4 + 1048576;
    float* k2 = h5 + 524288;
    float* k3 = k2 + 294912;
    float* k4 = k3 + 73728;
    float* k5 = k4 + 18432;

    PFN_encode enc = nullptr;
    cudaDriverEntryPointQueryResult qres;
#if CUDART_VERSION >= 12050
    cudaGetDriverEntryPointByVersion("cuTensorMapEncodeTiled", (void**)&enc, 12000,
                                     cudaEnableDefault, &qres);
#else
    cudaGetDriverEntryPoint("cuTensorMapEncodeTiled", (void**)&enc,
                            cudaEnableDefault, &qres);
#endif
    // s1 quad maps: box 40x34; s2v: 40x65; s2: 40x33; s1_16: 48x18
    make_map(enc, &h_maps[0],  x,    256, 256, 2,    40, 34);
    make_map(enc, &h_maps[1],  bufA, 256, 256, 128,  40, 34);
    make_map(enc, &h_maps[2],  h1,   256, 256, 128,  40, 65);
    make_map(enc, &h_maps[3],  bufA, 128, 128, 128,  40, 34);
    make_map(enc, &h_maps[4],  bufB, 128, 128, 256,  40, 34);
    make_map(enc, &h_maps[5],  h2,   128, 128, 256,  40, 65);
    make_map(enc, &h_maps[6],  bufA, 64, 64, 256,    40, 34);
    make_map(enc, &h_maps[7],  bufB, 64, 64, 512,    40, 34);
    make_map(enc, &h_maps[8],  h3,   64, 64, 512,    40, 65);
    make_map(enc, &h_maps[9],  bufA, 32, 32, 512,    40, 34);
    make_map(enc, &h_maps[10], bufB, 32, 32, 1024,   40, 34);
    make_map(enc, &h_maps[11], h4,   32, 32, 1024,   40, 33);
    make_map(enc, &h_maps[12], bufA, 16, 16, 1024,   48, 18);
    make_map(enc, &h_maps[13], bufB, 16, 16, 2048,   48, 18);

    transpose_all_kernel<<<(21971520 + 255) / 256, 256>>>(wp, wT);

    const float KC2 = 1e-4f * 1e-4f;

    // Stage 1
    conv_s1_l(h_maps[0], wt[0], B14[0], nullptr, bufA, 1,  64, 256, 256, 1);
    conv_s1_l(h_maps[1], wt[1], B14[1], nullptr, h1,   64, 64, 256, 256, 1);
    conv_s2_l(h_maps[2], wt[2], B14[2], nullptr, bufA, 64, 64, 256, 256, 1);

    // Stage 2
    pac_layer(bufA, k2, 64, 128, 128, KC2);
    conv_s1_l(h_maps[3], wt[3], B14[3], k2, bufB, 64,  128, 128, 128, 1);
    conv_s1_l(h_maps[4], wt[4], B14[4], k2, h2,   128, 128, 128, 128, 1);
    conv_s2_l(h_maps[5], wt[5], B14[5], k2, bufA, 128, 128, 128, 128, 1);

    // Stage 3
    pac_layer(bufA, k3, 128, 64, 64, KC2);
    conv_s1_l(h_maps[6], wt[6], B14[6], k3, bufB, 128, 256, 64, 64, 1);
    conv_s1_l(h_maps[7], wt[7], B14[7], k3, h3,   256, 256, 64, 64, 1);
    conv_s2_l(h_maps[8], wt[8], B14[8], k3, bufA, 256, 256, 64, 64, 4);   // split-K

    // Stage 4
    pac_layer(bufA, k4, 256, 32, 32, 4.0f);
    conv_s1_l(h_maps[9],  wt[9],  B14[9],  k4, bufB, 256, 512, 32, 32, 4);  // split-K
    conv_s1_l(h_maps[10], wt[10], B14[10], k4, h4,   512, 512, 32, 32, 4);  // split-K
    conv_s2_l(h_maps[11], wt[11], B14[11], k4, bufA, 512, 512, 32, 32, 4);  // split-K

    // Stage 5
    pac_layer(bufA, k5, 512, 16, 16, KC2);
    conv_s1_l(h_maps[12], wt[12], B14[12], k5, bufB, 512,  1024, 16, 16, 4); // split-K
    conv_s1_l(h_maps[13], wt[13], B14[13], k5, h5,   1024, 1024, 16, 16, 4); // split-K
}

// round 14
// speedup vs baseline: 1.1315x; 1.0184x over previous
#include <cuda.h>
#include <cuda_runtime.h>
#include <cstdint>

typedef unsigned long long u64;

__device__ __align__(256) float g_bufA[8388608];
__device__ __align__(256) float g_bufB[4194304];
__device__ __align__(256) float g_wT [21971520];   // transposed weights [c][ij][o]
__device__ __align__(256) float g_part[4194304];   // split-K partial sums

__device__ __forceinline__ void cp_async16(uint32_t saddr, const float* gptr) {
    asm volatile("cp.async.cg.shared.global [%0], [%1], 16;" :: "r"(saddr), "l"(gptr));
}
#define CP_COMMIT() asm volatile("cp.async.commit_group;" ::: "memory")
#define CP_WAIT0()  asm volatile("cp.async.wait_group 0;" ::: "memory")
#define FFMA2(acc, w, v) asm("fma.rn.f32x2 %0, %1, %2, %0;" : "+l"(acc) : "l"(w), "l"(v))
#define PACK2(d, a, b)   asm("mov.b64 %0, {%1, %2};" : "=l"(d) : "f"(a), "f"(b))
#define UNPACK2(lo, hi, p) asm("mov.b64 {%0, %1}, %2;" : "=f"(lo), "=f"(hi) : "l"(p))

#define MBAR_INIT(mbar, cnt) \
    asm volatile("mbarrier.init.shared.b64 [%0], %1;" :: "r"(mbar), "r"(cnt) : "memory")
#define MBAR_EXPECT(mbar, bytes) \
    asm volatile("mbarrier.arrive.expect_tx.shared.b64 _, [%0], %1;" :: "r"(mbar), "r"(bytes) : "memory")
#define MBAR_WAIT(mbar, par) do { \
    asm volatile( \
        "{\n\t.reg .pred P1;\n\t" \
        "WAIT_LOOP_%=:\n\t" \
        "mbarrier.try_wait.parity.acquire.cta.shared::cta.b64 P1, [%0], %1, 0x989680;\n\t" \
        "@P1 bra.uni WAIT_DONE_%=;\n\t" \
        "bra.uni WAIT_LOOP_%=;\n\t" \
        "WAIT_DONE_%=:\n\t}" \
        :: "r"(mbar), "r"(par) : "memory"); \
} while(0)
#define TMA3D(dst, tmapp, cx, cy, cz, mbar) \
    asm volatile("cp.async.bulk.tensor.3d.shared::cta.global.tile.mbarrier::complete_tx::bytes " \
        "[%0], [%1, {%2, %3, %4}], [%5];" \
        :: "r"(dst), "l"(tmapp), "r"(cx), "r"(cy), "r"(cz), "r"(mbar) : "memory")

// ─── fused weight transpose ───
struct WPtrs { const float* p[14]; };

__global__ void transpose_all_kernel(WPtrs wp, float* __restrict__ wt)
{
    const int i = blockIdx.x * 256 + threadIdx.x;
    if (i >= 21971520) return;
    const int CiA[14] = {1,64,64, 64,128,128, 128,256,256, 256,512,512, 512,1024};
    const int CoA[14] = {64,64,64, 128,128,128, 256,256,256, 512,512,512, 1024,1024};
    const int OFF[15] = {0,576,37440,74304,148032,295488,442944,737856,1327680,
                         1917504,3097152,5456448,7815744,12534336,21971520};
    int l = 0;
    #pragma unroll
    for (int k = 1; k < 14; k++) if (i >= OFF[k]) l = k;
    int j = i - OFF[l];
    int Co = CoA[l], Ci = CiA[l];
    int o = j % Co;
    int cij = j / Co;
    int c = cij / 9, ij = cij % 9;
    wt[i] = wp.p[l][((size_t)o * Ci + c) * 9 + ij];
}

__global__ void reduce_brelu(const float* __restrict__ part, const float* __restrict__ bias,
                             float* __restrict__ out, int Co, int HW, int S, int tot)
{
    int idx = blockIdx.x * 256 + threadIdx.x;
    if (idx >= tot) return;
    int o = (idx / HW) % Co;
    float v = bias[o];
    for (int s = 0; s < S; s++) v += part[(size_t)s * tot + idx];
    out[idx] = v > 0.0f ? v : 0.0f;
}

#define TAP16R(w0, w1, w2, w3, vv, A)                                  \
    {                                                                  \
        FFMA2((A)[0], (w0).x, vv); FFMA2((A)[1], (w0).y, vv);          \
        FFMA2((A)[2], (w1).x, vv); FFMA2((A)[3], (w1).y, vv);          \
        FFMA2((A)[4], (w2).x, vv); FFMA2((A)[5], (w2).y, vv);          \
        FFMA2((A)[6], (w3).x, vv); FFMA2((A)[7], (w3).y, vv);          \
    }

// ─── stride-1 quad: 32x32 tile, 2x2 px/thread, 8 outs ───
template<int CB>
__global__ void __launch_bounds__(256) conv_s1q(
    const __grid_constant__ CUtensorMap tmap, const float* __restrict__ wt,
    const float* __restrict__ bias, const float* __restrict__ kern,
    float* __restrict__ out, int Ci, int Co, int H, int W, int tilesX,
    int Csub, int S)
{
    constexpr int PITCH = 40, TSZ = 34 * 40, CSZ = 1376;
    __shared__ __align__(128) float s_in[2][CB * CSZ];
    __shared__ __align__(16) float s_w[2][CB * 72];
    __shared__ __align__(8) unsigned long long s_mbar[2];

    const int tid = threadIdx.x;
    const int lx = tid % 16, ty = tid / 16;
    const int tX = blockIdx.x % tilesX, tY = blockIdx.x / tilesX;
    const int ocg = blockIdx.y;
    const int zz = blockIdx.z;
    const int b = zz & 1, sk = zz >> 1;
    const int cbase = sk * Csub;
    const int oh0 = tY * 32 + 2 * ty, ow0 = tX * 32 + 2 * lx;
    const size_t HW = (size_t)H * W;
    const int gr0 = tY * 32 - 1, gc0 = tX * 32 - 4;

    const uint32_t mb0 = (uint32_t)__cvta_generic_to_shared(&s_mbar[0]);
    if (tid == 0) { MBAR_INIT(mb0, 1); MBAR_INIT(mb0 + 8, 1); }

    float kk[4][9];
    if (kern) {
        const float* kp = kern + (size_t)b * 9 * HW + (size_t)oh0 * W + ow0;
        #pragma unroll
        for (int t = 0; t < 9; t++) {
            float2 r0 = *(const float2*)(kp + (size_t)t * HW);
            float2 r1 = *(const float2*)(kp + (size_t)t * HW + W);
            kk[0][t] = r0.x; kk[1][t] = r0.y;
            kk[2][t] = r1.x; kk[3][t] = r1.y;
        }
    } else {
        #pragma unroll
        for (int p = 0; p < 4; p++)
        #pragma unroll
        for (int t = 0; t < 9; t++) kk[p][t] = 1.0f;
    }

    u64 acc[16];
    #pragma unroll
    for (int p = 0; p < 16; p++) acc[p] = 0ull;

    const uint32_t sinA[2] = {(uint32_t)__cvta_generic_to_shared(&s_in[0][0]),
                              (uint32_t)__cvta_generic_to_shared(&s_in[1][0])};
    const uint32_t swA[2]  = {(uint32_t)__cvta_generic_to_shared(&s_w[0][0]),
                              (uint32_t)__cvta_generic_to_shared(&s_w[1][0])};
    const int NG = Csub / CB;

    const bool wval = tid < CB * 18;
    uint32_t woff = 0;
    const float* wsrc = wt;
    {
        int c = tid / 18, rem = tid % 18, ij = rem / 2, q = rem % 2;
        woff = (uint32_t)(c * 72 + ij * 8 + 4 * q) * 4u;
        wsrc = wt + ((size_t)(cbase + c) * 9 + ij) * Co + (size_t)ocg * 8 + 4 * q;
    }
    const size_t wstep = (size_t)CB * 9 * Co;

    __syncthreads();

    auto stage_in = [&](int g, int buf) {
        uint32_t mb = mb0 + buf * 8;
        MBAR_EXPECT(mb, (uint32_t)(CB * TSZ * 4));
        int plane = b * Ci + cbase + g * CB;
        #pragma unroll
        for (int c = 0; c < CB; c++)
            TMA3D(sinA[buf] + c * CSZ * 4, &tmap, gc0, gr0, plane + c, mb);
    };
    auto stage_w = [&](int buf) {
        if (wval) cp_async16(swA[buf] + woff, wsrc);
        wsrc += wstep;
    };

    if (tid == 0) stage_in(0, 0);
    stage_w(0);
    CP_COMMIT();

    const int base_off = (2 * ty) * PITCH + 2 * lx + 3;

    for (int g = 0; g < NG; g++) {
        MBAR_WAIT(mb0 + (g & 1) * 8, (g >> 1) & 1);
        CP_WAIT0();
        __syncthreads();
        if (g + 1 < NG) {
            if (tid == 0) stage_in(g + 1, (g + 1) & 1);
            stage_w((g + 1) & 1);
            CP_COMMIT();
        }
        const int buf = g & 1;

        #pragma unroll
        for (int c = 0; c < CB; c++) {
            const float* sp = &s_in[buf][c * CSZ + base_off];
            float x[4][4];
            #pragma unroll
            for (int r = 0; r < 4; r++) {
                const float* rp = sp + r * PITCH;
                x[r][0] = rp[0];
                float2 xm = *(const float2*)(rp + 1);
                x[r][1] = xm.x; x[r][2] = xm.y;
                x[r][3] = rp[3];
            }
            const ulonglong2* wq = reinterpret_cast<const ulonglong2*>(&s_w[buf][c * 72]);
            #pragma unroll
            for (int i = 0; i < 3; i++)
            #pragma unroll
            for (int j = 0; j < 3; j++) {
                const int t = 3 * i + j;
                ulonglong2 wa = wq[2 * t], wb = wq[2 * t + 1];
                float v00 = x[i][j]     * kk[0][t];
                float v01 = x[i][j + 1] * kk[1][t];
                float v10 = x[i + 1][j]     * kk[2][t];
                float v11 = x[i + 1][j + 1] * kk[3][t];
                u64 p00, p01, p10, p11;
                PACK2(p00, v00, v00);
                PACK2(p01, v01, v01);
                PACK2(p10, v10, v10);
                PACK2(p11, v11, v11);
                FFMA2(acc[0],  wa.x, p00); FFMA2(acc[1],  wa.y, p00);
                FFMA2(acc[2],  wb.x, p00); FFMA2(acc[3],  wb.y, p00);
                FFMA2(acc[4],  wa.x, p01); FFMA2(acc[5],  wa.y, p01);
                FFMA2(acc[6],  wb.x, p01); FFMA2(acc[7],  wb.y, p01);
                FFMA2(acc[8],  wa.x, p10); FFMA2(acc[9],  wa.y, p10);
                FFMA2(acc[10], wb.x, p10); FFMA2(acc[11], wb.y, p10);
                FFMA2(acc[12], wa.x, p11); FFMA2(acc[13], wa.y, p11);
                FFMA2(acc[14], wb.x, p11); FFMA2(acc[15], wb.y, p11);
            }
        }
    }

    if (S == 1) {
        #pragma unroll
        for (int q = 0; q < 4; q++) {
            int o0 = ocg * 8 + 2 * q;
            float a00, a01, a10, a11, a20, a21, a30, a31;
            UNPACK2(a00, a01, acc[q]);
            UNPACK2(a10, a11, acc[4 + q]);
            UNPACK2(a20, a21, acc[8 + q]);
            UNPACK2(a30, a31, acc[12 + q]);
            float b0 = bias[o0], b1 = bias[o0 + 1];
            float r00 = a00 + b0, r01 = a10 + b0, r02 = a20 + b0, r03 = a30 + b0;
            float r10 = a01 + b1, r11 = a11 + b1, r12 = a21 + b1, r13 = a31 + b1;
            r00 = r00 > 0.0f ? r00 : 0.0f; r01 = r01 > 0.0f ? r01 : 0.0f;
            r02 = r02 > 0.0f ? r02 : 0.0f; r03 = r03 > 0.0f ? r03 : 0.0f;
            r10 = r10 > 0.0f ? r10 : 0.0f; r11 = r11 > 0.0f ? r11 : 0.0f;
            r12 = r12 > 0.0f ? r12 : 0.0f; r13 = r13 > 0.0f ? r13 : 0.0f;
            float* p0 = &out[((size_t)(b * Co + o0)     * H + oh0) * W + ow0];
            float* p1 = &out[((size_t)(b * Co + o0 + 1) * H + oh0) * W + ow0];
            *(float2*)p0       = make_float2(r00, r01);
            *(float2*)(p0 + W) = make_float2(r02, r03);
            *(float2*)p1       = make_float2(r10, r11);
            *(float2*)(p1 + W) = make_float2(r12, r13);
        }
    } else {
        float* pp = out + (size_t)sk * 2 * Co * HW;
        #pragma unroll
        for (int q = 0; q < 4; q++) {
            int o0 = ocg * 8 + 2 * q;
            float a00, a01, a10, a11, a20, a21, a30, a31;
            UNPACK2(a00, a01, acc[q]);
            UNPACK2(a10, a11, acc[4 + q]);
            UNPACK2(a20, a21, acc[8 + q]);
            UNPACK2(a30, a31, acc[12 + q]);
            float* p0 = &pp[((size_t)(b * Co + o0)     * H + oh0) * W + ow0];
            float* p1 = &pp[((size_t)(b * Co + o0 + 1) * H + oh0) * W + ow0];
            *(float2*)p0       = make_float2(a00, a10);
            *(float2*)(p0 + W) = make_float2(a20, a30);
            *(float2*)p1       = make_float2(a01, a11);
            *(float2*)(p1 + W) = make_float2(a21, a31);
        }
    }
}

// ─── stride-1, 16x16 images: 1 px/thread, 16 outs, CB=8 ───
__global__ void __launch_bounds__(256) conv_s1_16(
    const __grid_constant__ CUtensorMap tmap, const float* __restrict__ wt,
    const float* __restrict__ bias, const float* __restrict__ kern,
    float* __restrict__ out, int Ci, int Co, int Csub, int S)
{
    constexpr int CB = 8, PITCH = 48, TSZ = 18 * 48, CSZ = 864;
    __shared__ __align__(128) float s_in[2][CB * CSZ];
    __shared__ __align__(16) float s_w[2][CB * 144];
    __shared__ __align__(8) unsigned long long s_mbar[2];

    const int tid = threadIdx.x;
    const int tx = tid % 16, ty = tid / 16;
    const int ocg = blockIdx.y;
    const int zz = blockIdx.z;
    const int b = zz & 1, sk = zz >> 1;
    const int cbase = sk * Csub;
    const size_t HW = 256;

    const uint32_t mb0 = (uint32_t)__cvta_generic_to_shared(&s_mbar[0]);
    if (tid == 0) { MBAR_INIT(mb0, 1); MBAR_INIT(mb0 + 8, 1); }

    float kreg[9];
    {
        const float* kp = kern + (size_t)b * 9 * HW + (size_t)ty * 16 + tx;
        #pragma unroll
        for (int t = 0; t < 9; t++) kreg[t] = kp[(size_t)t * HW];
    }

    u64 acc[8];
    #pragma unroll
    for (int p = 0; p < 8; p++) acc[p] = 0ull;

    const uint32_t sinA[2] = {(uint32_t)__cvta_generic_to_shared(&s_in[0][0]),
                              (uint32_t)__cvta_generic_to_shared(&s_in[1][0])};
    const uint32_t swA[2]  = {(uint32_t)__cvta_generic_to_shared(&s_w[0][0]),
                              (uint32_t)__cvta_generic_to_shared(&s_w[1][0])};
    const int NG = Csub / CB;

    const bool wval = tid < CB * 36 && tid < 256;
    uint32_t woff = 0;
    const float* wsrc = wt;
    {
        int c = tid / 36, rem = tid % 36, ij = rem / 4, q = rem % 4;
        woff = (uint32_t)(c * 144 + ij * 16 + 4 * q) * 4u;
        wsrc = wt + ((size_t)(cbase + c) * 9 + ij) * Co + (size_t)ocg * 16 + 4 * q;
    }
    // CB*36 = 288 > 256 threads: second pass slot
    const bool wval2 = (tid + 256) < CB * 36;
    uint32_t woff2 = 0;
    const float* wsrc2 = wt;
    {
        int s2i = tid + 256;
        int c = s2i / 36, rem = s2i % 36, ij = rem / 4, q = rem % 4;
        woff2 = (uint32_t)(c * 144 + ij * 16 + 4 * q) * 4u;
        wsrc2 = wt + ((size_t)(cbase + c) * 9 + ij) * Co + (size_t)ocg * 16 + 4 * q;
    }
    const size_t wstep = (size_t)CB * 9 * Co;

    __syncthreads();

    auto stage_in = [&](int g, int buf) {
        uint32_t mb = mb0 + buf * 8;
        MBAR_EXPECT(mb, (uint32_t)(CB * TSZ * 4));
        int plane = b * Ci + cbase + g * CB;
        #pragma unroll
        for (int c = 0; c < CB; c++)
            TMA3D(sinA[buf] + c * CSZ * 4, &tmap, -4, -1, plane + c, mb);
    };
    auto stage_w = [&](int buf) {
        if (wval)  cp_async16(swA[buf] + woff,  wsrc);
        if (wval2) cp_async16(swA[buf] + woff2, wsrc2);
        wsrc += wstep; wsrc2 += wstep;
    };

    if (tid == 0) stage_in(0, 0);
    stage_w(0);
    CP_COMMIT();

    const int base_off = ty * PITCH + tx + 3;

    for (int g = 0; g < NG; g++) {
        MBAR_WAIT(mb0 + (g & 1) * 8, (g >> 1) & 1);
        CP_WAIT0();
        __syncthreads();
        if (g + 1 < NG) {
            if (tid == 0) stage_in(g + 1, (g + 1) & 1);
            stage_w((g + 1) & 1);
            CP_COMMIT();
        }
        const int buf = g & 1;

        #pragma unroll
        for (int c = 0; c < CB; c++) {
            const float* sp = &s_in[buf][c * CSZ + base_off];
            const ulonglong2* wq = reinterpret_cast<const ulonglong2*>(&s_w[buf][c * 144]);
            #pragma unroll
            for (int t = 0; t < 9; t++) {
                ulonglong2 w0 = wq[4*t], w1 = wq[4*t+1], w2 = wq[4*t+2], w3 = wq[4*t+3];
                float v = sp[(t / 3) * PITCH + (t % 3)] * kreg[t];
                u64 vv;
                PACK2(vv, v, v);
                TAP16R(w0, w1, w2, w3, vv, acc);
            }
        }
    }

    if (S == 1) {
        #pragma unroll
        for (int p = 0; p < 8; p++) {
            int o = ocg * 16 + 2 * p;
            float lo, hi;
            UNPACK2(lo, hi, acc[p]);
            float v0 = lo + bias[o], v1 = hi + bias[o + 1];
            v0 = v0 > 0.0f ? v0 : 0.0f;
            v1 = v1 > 0.0f ? v1 : 0.0f;
            out[((size_t)(b * Co + o)     * 16 + ty) * 16 + tx] = v0;
            out[((size_t)(b * Co + o + 1) * 16 + ty) * 16 + tx] = v1;
        }
    } else {
        float* pp = out + (size_t)sk * 2 * Co * HW;
        #pragma unroll
        for (int p = 0; p < 8; p++) {
            int o = ocg * 16 + 2 * p;
            float lo, hi;
            UNPACK2(lo, hi, acc[p]);
            pp[((size_t)(b * Co + o)     * 16 + ty) * 16 + tx] = lo;
            pp[((size_t)(b * Co + o + 1) * 16 + ty) * 16 + tx] = hi;
        }
    }
}

// ─── stride-2 vertical-pair: 16x32 out tile, 2 px/thread, 16 outs, CB=4 ───
__global__ void __launch_bounds__(256) conv_s2v(
    const __grid_constant__ CUtensorMap tmap, const float* __restrict__ wt,
    const float* __restrict__ bias, const float* __restrict__ kern,
    float* __restrict__ out, int Ci, int Co, int H, int W, int tilesX,
    int Csub, int S)
{
    constexpr int CB = 4, PITCH = 40, TSZ = 65 * 40, CSZ = 2624;
    __shared__ __align__(128) float s_in[2][CB * CSZ];
    __shared__ __align__(16) float s_w[2][CB * 144];
    __shared__ __align__(8) unsigned long long s_mbar[2];

    const int tid = threadIdx.x;
    const int tx = tid % 16, ty = tid / 16;
    const int tX = blockIdx.x % tilesX, tY = blockIdx.x / tilesX;
    const int ocg = blockIdx.y;
    const int zz = blockIdx.z;
    const int b = zz & 1, sk = zz >> 1;
    const int cbase = sk * Csub;
    const int Hout = H / 2, Wout = W / 2;
    const int oh0 = tY * 32 + 2 * ty;
    const int ow = tX * 16 + tx;
    const size_t HW = (size_t)H * W;
    const int gr0 = tY * 64 - 1, gc0 = tX * 32 - 4;

    const uint32_t mb0 = (uint32_t)__cvta_generic_to_shared(&s_mbar[0]);
    if (tid == 0) { MBAR_INIT(mb0, 1); MBAR_INIT(mb0 + 8, 1); }

    float kA[9], kB[9];
    if (kern) {
        const float* kp = kern + (size_t)b * 9 * HW + (size_t)(oh0 * 2) * W + ow * 2;
        #pragma unroll
        for (int t = 0; t < 9; t++) {
            kA[t] = kp[(size_t)t * HW];
            kB[t] = kp[(size_t)t * HW + 2 * W];
        }
    } else {
        #pragma unroll
        for (int t = 0; t < 9; t++) { kA[t] = 1.0f; kB[t] = 1.0f; }
    }

    u64 accA[8], accB[8];
    #pragma unroll
    for (int p = 0; p < 8; p++) { accA[p] = 0ull; accB[p] = 0ull; }

    const uint32_t sinA[2] = {(uint32_t)__cvta_generic_to_shared(&s_in[0][0]),
                              (uint32_t)__cvta_generic_to_shared(&s_in[1][0])};
    const uint32_t swA[2]  = {(uint32_t)__cvta_generic_to_shared(&s_w[0][0]),
                              (uint32_t)__cvta_generic_to_shared(&s_w[1][0])};
    const int NG = Csub / CB;

    const bool wval = tid < CB * 36;
    uint32_t woff = 0;
    const float* wsrc = wt;
    {
        int c = tid / 36, rem = tid % 36, ij = rem / 4, q = rem % 4;
        woff = (uint32_t)(c * 144 + ij * 16 + 4 * q) * 4u;
        wsrc = wt + ((size_t)(cbase + c) * 9 + ij) * Co + (size_t)ocg * 16 + 4 * q;
    }
    const size_t wstep = (size_t)CB * 9 * Co;

    __syncthreads();

    auto stage_in = [&](int g, int buf) {
        uint32_t mb = mb0 + buf * 8;
        MBAR_EXPECT(mb, (uint32_t)(CB * TSZ * 4));
        int plane = b * Ci + cbase + g * CB;
        #pragma unroll
        for (int c = 0; c < CB; c++)
            TMA3D(sinA[buf] + c * CSZ * 4, &tmap, gc0, gr0, plane + c, mb);
    };
    auto stage_w = [&](int buf) {
        if (wval) cp_async16(swA[buf] + woff, wsrc);
        wsrc += wstep;
    };

    if (tid == 0) stage_in(0, 0);
    stage_w(0);
    CP_COMMIT();

    const int base_off = (4 * ty) * PITCH + 2 * tx + 3;

    for (int g = 0; g < NG; g++) {
        MBAR_WAIT(mb0 + (g & 1) * 8, (g >> 1) & 1);
        CP_WAIT0();
        __syncthreads();
        if (g + 1 < NG) {
            if (tid == 0) stage_in(g + 1, (g + 1) & 1);
            stage_w((g + 1) & 1);
            CP_COMMIT();
        }
        const int buf = g & 1;

        #pragma unroll
        for (int c = 0; c < CB; c++) {
            const float* sp = &s_in[buf][c * CSZ + base_off];
            float x[5][3];
            #pragma unroll
            for (int r = 0; r < 5; r++) {
                const float* rp = sp + r * PITCH;
                x[r][0] = rp[0]; x[r][1] = rp[1]; x[r][2] = rp[2];
            }
            const ulonglong2* wq = reinterpret_cast<const ulonglong2*>(&s_w[buf][c * 144]);
            #pragma unroll
            for (int i = 0; i < 3; i++)
            #pragma unroll
            for (int j = 0; j < 3; j++) {
                const int t = 3 * i + j;
                ulonglong2 w0 = wq[4*t], w1 = wq[4*t+1], w2 = wq[4*t+2], w3 = wq[4*t+3];
                float vA = x[i][j]     * kA[t];
                float vB = x[i + 2][j] * kB[t];
                u64 vvA, vvB;
                PACK2(vvA, vA, vA);
                PACK2(vvB, vB, vB);
                TAP16R(w0, w1, w2, w3, vvA, accA);
                TAP16R(w0, w1, w2, w3, vvB, accB);
            }
        }
    }

    if (S == 1) {
        #pragma unroll
        for (int p = 0; p < 8; p++) {
            int o = ocg * 16 + 2 * p;
            float a0, a1, b0v, b1v;
            UNPACK2(a0, a1, accA[p]);
            UNPACK2(b0v, b1v, accB[p]);
            float bias0 = bias[o], bias1 = bias[o + 1];
            float p00 = a0 + bias0, p01 = b0v + bias0;
            float p10 = a1 + bias1, p11 = b1v + bias1;
            p00 = p00 > 0.0f ? p00 : 0.0f;
            p01 = p01 > 0.0f ? p01 : 0.0f;
            p10 = p10 > 0.0f ? p10 : 0.0f;
            p11 = p11 > 0.0f ? p11 : 0.0f;
            float* o0p = &out[((size_t)(b * Co + o)     * Hout + oh0) * Wout + ow];
            float* o1p = &out[((size_t)(b * Co + o + 1) * Hout + oh0) * Wout + ow];
            o0p[0] = p00; o0p[Wout] = p01;
            o1p[0] = p10; o1p[Wout] = p11;
        }
    } else {
        float* pp = out + (size_t)sk * 2 * Co * Hout * Wout;
        #pragma unroll
        for (int p = 0; p < 8; p++) {
            int o = ocg * 16 + 2 * p;
            float a0, a1, b0v, b1v;
            UNPACK2(a0, a1, accA[p]);
            UNPACK2(b0v, b1v, accB[p]);
            float* o0p = &pp[((size_t)(b * Co + o)     * Hout + oh0) * Wout + ow];
            float* o1p = &pp[((size_t)(b * Co + o + 1) * Hout + oh0) * Wout + ow];
            o0p[0] = a0; o0p[Wout] = b0v;
            o1p[0] = a1; o1p[Wout] = b1v;
        }
    }
}

// ─── stride-2 small (Hout<32): 16x16 out tile, 1 px/thread, 16 outs, CB=4 ───
__global__ void __launch_bounds__(256) conv_s2(
    const __grid_constant__ CUtensorMap tmap, const float* __restrict__ wt,
    const float* __restrict__ bias, const float* __restrict__ kern,
    float* __restrict__ out, int Ci, int Co, int H, int W, int tilesX,
    int Csub, int S)
{
    constexpr int CB = 4, PITCH = 40, TSZ = 33 * 40, CSZ = 1344;
    __shared__ __align__(128) float s_in[2][CB * CSZ];
    __shared__ __align__(16) float s_w[2][CB * 144];
    __shared__ __align__(8) unsigned long long s_mbar[2];

    const int tid = threadIdx.x;
    const int tx = tid % 16, ty = tid / 16;
    const int tX = blockIdx.x % tilesX, tY = blockIdx.x / tilesX;
    const int ocg = blockIdx.y;
    const int zz = blockIdx.z;
    const int b = zz & 1, sk = zz >> 1;
    const int cbase = sk * Csub;
    const int Hout = H / 2, Wout = W / 2;
    const int oh = tY * 16 + ty, ow = tX * 16 + tx;
    const size_t HW = (size_t)H * W;
    const int gr0 = tY * 32 - 1, gc0 = tX * 32 - 4;

    const uint32_t mb0 = (uint32_t)__cvta_generic_to_shared(&s_mbar[0]);
    if (tid == 0) { MBAR_INIT(mb0, 1); MBAR_INIT(mb0 + 8, 1); }

    float kreg[9];
    if (kern) {
        const float* kp = kern + (size_t)b * 9 * HW + (size_t)(oh * 2) * W + ow * 2;
        #pragma unroll
        for (int t = 0; t < 9; t++) kreg[t] = kp[(size_t)t * HW];
    } else {
        #pragma unroll
        for (int t = 0; t < 9; t++) kreg[t] = 1.0f;
    }

    u64 acc[8];
    #pragma unroll
    for (int p = 0; p < 8; p++) acc[p] = 0ull;

    const uint32_t sinA[2] = {(uint32_t)__cvta_generic_to_shared(&s_in[0][0]),
                              (uint32_t)__cvta_generic_to_shared(&s_in[1][0])};
    const uint32_t swA[2]  = {(uint32_t)__cvta_generic_to_shared(&s_w[0][0]),
                              (uint32_t)__cvta_generic_to_shared(&s_w[1][0])};
    const int NG = Csub / CB;

    const bool wval = tid < CB * 36;
    uint32_t woff = 0;
    const float* wsrc = wt;
    {
        int c = tid / 36, rem = tid % 36, ij = rem / 4, q = rem % 4;
        woff = (uint32_t)(c * 144 + ij * 16 + 4 * q) * 4u;
        wsrc = wt + ((size_t)(cbase + c) * 9 + ij) * Co + (size_t)ocg * 16 + 4 * q;
    }
    const size_t wstep = (size_t)CB * 9 * Co;

    __syncthreads();

    auto stage_in = [&](int g, int buf) {
        uint32_t mb = mb0 + buf * 8;
        MBAR_EXPECT(mb, (uint32_t)(CB * TSZ * 4));
        int plane = b * Ci + cbase + g * CB;
        #pragma unroll
        for (int c = 0; c < CB; c++)
            TMA3D(sinA[buf] + c * CSZ * 4, &tmap, gc0, gr0, plane + c, mb);
    };
    auto stage_w = [&](int buf) {
        if (wval) cp_async16(swA[buf] + woff, wsrc);
        wsrc += wstep;
    };

    if (tid == 0) stage_in(0, 0);
    stage_w(0);
    CP_COMMIT();

    const int base_off = (2 * ty) * PITCH + 2 * tx + 3;

    for (int g = 0; g < NG; g++) {
        MBAR_WAIT(mb0 + (g & 1) * 8, (g >> 1) & 1);
        CP_WAIT0();
        __syncthreads();
        if (g + 1 < NG) {
            if (tid == 0) stage_in(g + 1, (g + 1) & 1);
            stage_w((g + 1) & 1);
            CP_COMMIT();
        }
        const int buf = g & 1;

        #pragma unroll
        for (int c = 0; c < CB; c++) {
            const float* sp = &s_in[buf][c * CSZ + base_off];
            const ulonglong2* wq = reinterpret_cast<const ulonglong2*>(&s_w[buf][c * 144]);
            #pragma unroll
            for (int t = 0; t < 9; t++) {
                ulonglong2 w0 = wq[4*t], w1 = wq[4*t+1], w2 = wq[4*t+2], w3 = wq[4*t+3];
                float v = sp[(t / 3) * PITCH + (t % 3)] * kreg[t];
                u64 vv;
                PACK2(vv, v, v);
                TAP16R(w0, w1, w2, w3, vv, acc);
            }
        }
    }

    if (S == 1) {
        #pragma unroll
        for (int p = 0; p < 8; p++) {
            int o = ocg * 16 + 2 * p;
            float lo, hi;
            UNPACK2(lo, hi, acc[p]);
            float v0 = lo + bias[o], v1 = hi + bias[o + 1];
            v0 = v0 > 0.0f ? v0 : 0.0f;
            v1 = v1 > 0.0f ? v1 : 0.0f;
            out[((size_t)(b * Co + o)     * Hout + oh) * Wout + ow] = v0;
            out[((size_t)(b * Co + o + 1) * Hout + oh) * Wout + ow] = v1;
        }
    } else {
        float* pp = out + (size_t)sk * 2 * Co * Hout * Wout;
        #pragma unroll
        for (int p = 0; p < 8; p++) {
            int o = ocg * 16 + 2 * p;
            float lo, hi;
            UNPACK2(lo, hi, acc[p]);
            pp[((size_t)(b * Co + o)     * Hout + oh) * Wout + ow] = lo;
            pp[((size_t)(b * Co + o + 1) * Hout + oh) * Wout + ow] = hi;
        }
    }
}

__global__ void pac_gauss_kernel(const float* __restrict__ f, float* __restrict__ out,
                                 int C, int H, int W, float coeff2)
{
    const int b = blockIdx.z;
    const int idx = blockIdx.x * blockDim.x + threadIdx.x;
    if (idx >= H * W) return;
    const int h = idx / W, w = idx % W;

    float acc[9];
    #pragma unroll
    for (int t = 0; t < 9; t++) acc[t] = 0.0f;

    const float* fb = f + (size_t)b * C * H * W;
    for (int c = 0; c < C; c++) {
        const float* fc = fb + (size_t)c * H * W;
        float ctr = fc[idx];
        #pragma unroll
        for (int i = 0; i < 3; i++)
        #pragma unroll
        for (int j = 0; j < 3; j++) {
            int hh = h + i - 1, ww = w + j - 1;
            float nb = (hh >= 0 && hh < H && ww >= 0 && ww < W) ? fc[hh * W + ww] : 0.0f;
            float d = nb - ctr;
            acc[i * 3 + j] += d * d;
        }
    }

    float* ob = out + (size_t)b * 9 * H * W;
    #pragma unroll
    for (int t = 0; t < 9; t++)
        ob[(size_t)t * H * W + idx] = expf(-0.5f * coeff2 * acc[t]);
}

// ─── host side ───

typedef CUresult (CUDAAPI *PFN_encode)(
    CUtensorMap*, CUtensorMapDataType, cuuint32_t, void*,
    const cuuint64_t*, const cuuint64_t*, const cuuint32_t*, const cuuint32_t*,
    CUtensorMapInterleave, CUtensorMapSwizzle, CUtensorMapL2promotion,
    CUtensorMapFloatOOBfill);

static CUtensorMap h_maps[14];
static float* g_part_ptr;

static void make_map(PFN_encode enc, CUtensorMap* m, const void* base,
                     int W, int H, int planes, int boxw, int boxh)
{
    cuuint64_t dims[3] = {(cuuint64_t)W, (cuuint64_t)H, (cuuint64_t)planes};
    cuuint64_t strides[2] = {(cuuint64_t)W * 4, (cuuint64_t)W * H * 4};
    cuuint32_t box[3] = {(cuuint32_t)boxw, (cuuint32_t)boxh, 1};
    cuuint32_t es[3] = {1, 1, 1};
    enc(m, CU_TENSOR_MAP_DATA_TYPE_FLOAT32, 3, const_cast<void*>(base),
        dims, strides, box, es,
        CU_TENSOR_MAP_INTERLEAVE_NONE, CU_TENSOR_MAP_SWIZZLE_NONE,
        CU_TENSOR_MAP_L2_PROMOTION_L2_128B, CU_TENSOR_MAP_FLOAT_OOB_FILL_NONE);
}

static void conv_s1_l(const CUtensorMap& m, const float* wt, const float* b,
                      const float* kern, float* out, int Ci, int Co, int H, int W, int S)
{
    float* dst = (S > 1) ? g_part_ptr : out;
    if (W >= 32) {
        int tilesX = W / 32;
        dim3 grid(tilesX * (H / 32), Co / 8, 2 * S);
        if ((Ci / S) % 8 == 0)
            conv_s1q<8><<<grid, 256>>>(m, wt, b, kern, dst, Ci, Co, H, W, tilesX, Ci / S, S);
        else
            conv_s1q<1><<<grid, 256>>>(m, wt, b, kern, dst, Ci, Co, H, W, tilesX, Ci / S, S);
    } else {
        dim3 grid(1, Co / 16, 2 * S);
        conv_s1_16<<<grid, 256>>>(m, wt, b, kern, dst, Ci, Co, Ci / S, S);
    }
    if (S > 1) {
        int tot = 2 * Co * H * W;
        reduce_brelu<<<(tot + 255) / 256, 256>>>(g_part_ptr, b, out, Co, H * W, S, tot);
    }
}

static void conv_s2_l(const CUtensorMap& m, const float* wt, const float* b,
                      const float* kern, float* out, int Ci, int Co, int H, int W, int S)
{
    int Hout = H / 2, Wout = W / 2;
    float* dst = (S > 1) ? g_part_ptr : out;
    if (Hout >= 32) {
        int tilesX = Wout / 16;
        dim3 grid(tilesX * (Hout / 32), Co / 16, 2 * S);
        conv_s2v<<<grid, 256>>>(m, wt, b, kern, dst, Ci, Co, H, W, tilesX, Ci / S, S);
    } else {
        int tilesX = W / 32;
        dim3 grid(tilesX * (H / 32), Co / 16, 2 * S);
        conv_s2<<<grid, 256>>>(m, wt, b, kern, dst, Ci, Co, H, W, tilesX, Ci / S, S);
    }
    if (S > 1) {
        int tot = 2 * Co * Hout * Wout;
        reduce_brelu<<<(tot + 255) / 256, 256>>>(g_part_ptr, b, out, Co, Hout * Wout, S, tot);
    }
}

static void pac_layer(const float* f, float* out, int C, int H, int W, float coeff2)
{
    int hw = H * W;
    dim3 grid((hw + 255) / 256, 1, 2);
    pac_gauss_kernel<<<grid, 256>>>(f, out, C, H, W, coeff2);
}

extern "C" void kernel_launch(void* const* d_in, const int* in_sizes, int n_in,
                              void* d_out, int out_size)
{
    const float* x = (const float*)d_in[0];
    WPtrs wp;
    const float* B14[14];
    for (int i = 0; i < 14; i++) {
        wp.p[i] = (const float*)d_in[1 + 2 * i];
        B14[i]  = (const float*)d_in[2 + 2 * i];
    }

    float* bufA; float* bufB; float* wT;
    cudaGetSymbolAddress((void**)&bufA, g_bufA);
    cudaGetSymbolAddress((void**)&bufB, g_bufB);
    cudaGetSymbolAddress((void**)&wT,  g_wT);
    cudaGetSymbolAddress((void**)&g_part_ptr, g_part);

    static const size_t OFF[15] = {0,576,37440,74304,148032,295488,442944,737856,1327680,
                                   1917504,3097152,5456448,7815744,12534336,21971520};
    const float* wt[14];
    for (int l = 0; l < 14; l++) wt[l] = wT + OFF[l];

    float* out = (float*)d_out;
    float* h1 = out;
    float* h2 = h1 + 8388608;
    float* h3 = h2 + 4194304;
    float* h4 = h3 + 2097152;
    float* h5 = h4 + 1048576;
    float* k2 = h5 + 524288;
    float* k3 = k2 + 294912;
    float* k4 = k3 + 73728;
    float* k5 = k4 + 18432;

    PFN_encode enc = nullptr;
    cudaDriverEntryPointQueryResult qres;
#if CUDART_VERSION >= 12050
    cudaGetDriverEntryPointByVersion("cuTensorMapEncodeTiled", (void**)&enc, 12000,
                                     cudaEnableDefault, &qres);
#else
    cudaGetDriverEntryPoint("cuTensorMapEncodeTiled", (void**)&enc,
                            cudaEnableDefault, &qres);
#endif
    make_map(enc, &h_maps[0],  x,    256, 256, 2,    40, 34);
    make_map(enc, &h_maps[1],  bufA, 256, 256, 128,  40, 34);
    make_map(enc, &h_maps[2],  h1,   256, 256, 128,  40, 65);
    make_map(enc, &h_maps[3],  bufA, 128, 128, 128,  40, 34);
    make_map(enc, &h_maps[4],  bufB, 128, 128, 256,  40, 34);
    make_map(enc, &h_maps[5],  h2,   128, 128, 256,  40, 65);
    make_map(enc, &h_maps[6],  bufA, 64, 64, 256,    40, 34);
    make_map(enc, &h_maps[7],  bufB, 64, 64, 512,    40, 34);
    make_map(enc, &h_maps[8],  h3,   64, 64, 512,    40, 65);
    make_map(enc, &h_maps[9],  bufA, 32, 32, 512,    40, 34);
    make_map(enc, &h_maps[10], bufB, 32, 32, 1024,   40, 34);
    make_map(enc, &h_maps[11], h4,   32, 32, 1024,   40, 33);
    make_map(enc, &h_maps[12], bufA, 16, 16, 1024,   48, 18);
    make_map(enc, &h_maps[13], bufB, 16, 16, 2048,   48, 18);

    transpose_all_kernel<<<(21971520 + 255) / 256, 256>>>(wp, wT);

    const float KC2 = 1e-4f * 1e-4f;

    // Stage 1
    conv_s1_l(h_maps[0], wt[0], B14[0], nullptr, bufA, 1,  64, 256, 256, 1);
    conv_s1_l(h_maps[1], wt[1], B14[1], nullptr, h1,   64, 64, 256, 256, 1);
    conv_s2_l(h_maps[2], wt[2], B14[2], nullptr, bufA, 64, 64, 256, 256, 1);

    // Stage 2
    pac_layer(bufA, k2, 64, 128, 128, KC2);
    conv_s1_l(h_maps[3], wt[3], B14[3], k2, bufB, 64,  128, 128, 128, 1);
    conv_s1_l(h_maps[4], wt[4], B14[4], k2, h2,   128, 128, 128, 128, 1);
    conv_s2_l(h_maps[5], wt[5], B14[5], k2, bufA, 128, 128, 128, 128, 1);

    // Stage 3
    pac_layer(bufA, k3, 128, 64, 64, KC2);
    conv_s1_l(h_maps[6], wt[6], B14[6], k3, bufB, 128, 256, 64, 64, 1);
    conv_s1_l(h_maps[7], wt[7], B14[7], k3, h3,   256, 256, 64, 64, 1);
    conv_s2_l(h_maps[8], wt[8], B14[8], k3, bufA, 256, 256, 64, 64, 4);   // split-K

    // Stage 4
    pac_layer(bufA, k4, 256, 32, 32, 4.0f);
    conv_s1_l(h_maps[9],  wt[9],  B14[9],  k4, bufB, 256, 512, 32, 32, 4);  // split-K
    conv_s1_l(h_maps[10], wt[10], B14[10], k4, h4,   512, 512, 32, 32, 4);  // split-K
    conv_s2_l(h_maps[11], wt[11], B14[11], k4, bufA, 512, 512, 32, 32, 4);  // split-K

    // Stage 5
    pac_layer(bufA, k5, 512, 16, 16, KC2);
    conv_s1_l(h_maps[12], wt[12], B14[12], k5, bufB, 512,  1024, 16, 16, 4); // split-K
    conv_s1_l(h_maps[13], wt[13], B14[13], k5, h5,   1024, 1024, 16, 16, 4); // split-K
}